// round 13
// baseline (speedup 1.0000x reference)
#include <cuda_runtime.h>
#include <cuda_fp16.h>
#include <math.h>
#include <stdint.h>

// Problem constants
#define BB 2
#define TT 2048
#define DD 1024
#define HH 16
#define HSZ 64
#define FFD 16384
#define MR (BB*TT)          // 4096 rows

// ---------------------------------------------------------------------------
// Scratch (static device globals; no runtime allocation)
// ---------------------------------------------------------------------------
__device__ float g_buf[(size_t)MR * DD];         // 16 MB
__device__ float g_ln1[(size_t)MR * DD];         // 16 MB
__device__ __half g_qkvh[(size_t)MR * 3 * DD];   // 25 MB
__device__ __half g_xh[(size_t)MR * DD];
__device__ __half g_atth[(size_t)MR * DD];
__device__ __half g_ln1h[(size_t)MR * DD];
__device__ __half g_ff1h[(size_t)MR * FFD];      // 128 MB
__device__ __half g_wqkvT[(size_t)3 * DD * DD];
__device__ __half g_wfcT[(size_t)DD * DD];
__device__ __half g_wff1T[(size_t)FFD * DD];
__device__ __half g_wff2T[(size_t)DD * FFD];

// ---------------------------------------------------------------------------
// PTX helpers (plain sm_100 legal: mma.sync + cp.async + ldmatrix only)
// ---------------------------------------------------------------------------
__device__ __forceinline__ uint32_t smem_u32(const void* p) {
    uint32_t a;
    asm("{ .reg .u64 t; cvta.to.shared.u64 t, %1; cvt.u32.u64 %0, t; }" : "=r"(a) : "l"(p));
    return a;
}
__device__ __forceinline__ void cp16(uint32_t dst, const void* src) {
    asm volatile("cp.async.cg.shared.global [%0], [%1], 16;" :: "r"(dst), "l"(src) : "memory");
}
#define CP_COMMIT() asm volatile("cp.async.commit_group;" ::: "memory")
#define CP_WAIT(n)  asm volatile("cp.async.wait_group %0;" :: "n"(n) : "memory")

__device__ __forceinline__ void mma_f16(float* c, const uint32_t* a, const uint32_t* b) {
    asm volatile("mma.sync.aligned.m16n8k16.row.col.f32.f16.f16.f32 "
        "{%0,%1,%2,%3}, {%4,%5,%6,%7}, {%8,%9}, {%0,%1,%2,%3};"
        : "+f"(c[0]), "+f"(c[1]), "+f"(c[2]), "+f"(c[3])
        : "r"(a[0]), "r"(a[1]), "r"(a[2]), "r"(a[3]), "r"(b[0]), "r"(b[1]));
}
__device__ __forceinline__ void ldmx4(uint32_t& r0, uint32_t& r1, uint32_t& r2, uint32_t& r3,
                                      uint32_t addr) {
    asm volatile("ldmatrix.sync.aligned.m8n8.x4.shared.b16 {%0,%1,%2,%3}, [%4];"
        : "=r"(r0), "=r"(r1), "=r"(r2), "=r"(r3) : "r"(addr));
}
__device__ __forceinline__ void ldmx4t(uint32_t& r0, uint32_t& r1, uint32_t& r2, uint32_t& r3,
                                       uint32_t addr) {
    asm volatile("ldmatrix.sync.aligned.m8n8.x4.trans.shared.b16 {%0,%1,%2,%3}, [%4];"
        : "=r"(r0), "=r"(r1), "=r"(r2), "=r"(r3) : "r"(addr));
}
__device__ __forceinline__ uint32_t packh2(float a, float b) {
    __half2 h = __floats2half2_rn(a, b);
    return *(uint32_t*)&h;
}

// ---------------------------------------------------------------------------
// Weight convert + transpose: Wt[n][k] = (half)W[k][n]
// ---------------------------------------------------------------------------
__global__ __launch_bounds__(256) void wtcvt_kernel(
    const float* __restrict__ W, __half* __restrict__ Wt, int K, int N)
{
    __shared__ float t[32][33];
    const int k0 = blockIdx.x * 32, n0 = blockIdx.y * 32;
    const int tx = threadIdx.x & 31, ty = threadIdx.x >> 5;   // 32 x 8
#pragma unroll
    for (int i = 0; i < 4; i++)
        t[ty + 8 * i][tx] = W[(size_t)(k0 + ty + 8 * i) * N + n0 + tx];
    __syncthreads();
#pragma unroll
    for (int i = 0; i < 4; i++)
        Wt[(size_t)(n0 + ty + 8 * i) * K + k0 + tx] = __float2half(t[tx][ty + 8 * i]);
}

// x fp32 -> fp16 (8 elements per thread)
__global__ __launch_bounds__(256) void f2h_kernel(
    const float* __restrict__ in, __half* __restrict__ out)
{
    size_t i = ((size_t)blockIdx.x * 256 + threadIdx.x) * 8;
    float4 a = *(const float4*)(in + i);
    float4 b = *(const float4*)(in + i + 4);
    __half2 h[4];
    h[0] = __floats2half2_rn(a.x, a.y);
    h[1] = __floats2half2_rn(a.z, a.w);
    h[2] = __floats2half2_rn(b.x, b.y);
    h[3] = __floats2half2_rn(b.z, b.w);
    *(float4*)(out + i) = *(float4*)h;
}

// ---------------------------------------------------------------------------
// fp16 tensor-core GEMM: C[M,N] = A[M,K] @ Wt^T (Wt is [N,K] fp16)
// BM=BN=128, BK=32, 256 threads (8 warps 2x4), warp tile 64x32.
// 2-stage cp.async ring, static smem, ldmatrix.x4 fragment loads.
// WRITEH: write fp16 to Ch instead of fp32 to C.   [R12-identical]
// ---------------------------------------------------------------------------
#define HROW 40                       // halves per smem row (32 + 8 pad)
#define ASTGB (128 * HROW * 2)        // 10240 B per operand stage
#define SSTGB (2 * ASTGB)             // 20480 B per stage (A+B)

template <int RELU, int HASRES, int WRITEH>
__global__ __launch_bounds__(256, 2) void hgemm(
    const __half* __restrict__ A, const __half* __restrict__ Bt,
    const float* __restrict__ bias, const float* __restrict__ res,
    float* __restrict__ C, __half* __restrict__ Ch, int M, int N, int Kt)
{
    __shared__ __half hs[2 * SSTGB / 2];     // 2 stages x 20480 B

    const int tid = threadIdx.x;
    const int wid = tid >> 5, lane = tid & 31;
    const int g = lane >> 2, tg = lane & 3;
    const int warp_m = wid & 1, warp_n = wid >> 1;
    const int bm = blockIdx.y * 128, bn = blockIdx.x * 128;
    const int NT = Kt / 32;
    const uint32_t sb = smem_u32(hs);

    // ldmatrix per-lane addresses (bytes, stage 0, kk 0)
    const int li = lane >> 3, lr = lane & 7;
    // A x4: m0=(r0,k0) m1=(r0+8,k0) m2=(r0,k8) m3=(r0+8,k8)
    const uint32_t a_lm = sb +
        (uint32_t)(((warp_m * 64 + (li & 1) * 8 + lr) * HROW + (li >> 1) * 8) * 2);
    // B x4: m0=(n0,k0) m1=(n0,k8) m2=(n0+8,k0) m3=(n0+8,k8)
    const uint32_t b_lm = sb + ASTGB +
        (uint32_t)(((warp_n * 32 + (li >> 1) * 8 + lr) * HROW + (li & 1) * 8) * 2);

    float acc[4][4][4] = {};

    const int c_row = tid >> 1;            // 0..127
    const int c_ch0 = (tid & 1) * 2;       // chunk base {0,2}; 16B chunks

#define HISSUE(it, s) do { \
        const int k0 = (it) * 32; \
        const uint32_t so = (uint32_t)(s) * SSTGB + (uint32_t)c_row * 80 + (uint32_t)c_ch0 * 16; \
        const __half* ag = A  + (size_t)(bm + c_row) * Kt + k0 + c_ch0 * 8; \
        const __half* bg = Bt + (size_t)(bn + c_row) * Kt + k0 + c_ch0 * 8; \
        cp16(sb + so,              ag); \
        cp16(sb + so + 16,         ag + 8); \
        cp16(sb + ASTGB + so,      bg); \
        cp16(sb + ASTGB + so + 16, bg + 8); \
    } while (0)

    HISSUE(0, 0); CP_COMMIT();
    HISSUE(1, 1); CP_COMMIT();

    for (int it = 0; it < NT; it++) {
        const int s = it & 1;
        CP_WAIT(1);
        __syncthreads();

        const uint32_t soff = (uint32_t)s * SSTGB;

#pragma unroll
        for (int kk = 0; kk < 2; kk++) {
            const uint32_t koff = soff + (uint32_t)kk * 32;   // 16 halves = 32 B
            uint32_t af[4][4], bf[4][2];
#pragma unroll
            for (int mt = 0; mt < 4; mt++)
                ldmx4(af[mt][0], af[mt][1], af[mt][2], af[mt][3],
                      a_lm + koff + (uint32_t)(mt * 16 * HROW * 2));
            ldmx4(bf[0][0], bf[0][1], bf[1][0], bf[1][1], b_lm + koff);
            ldmx4(bf[2][0], bf[2][1], bf[3][0], bf[3][1],
                  b_lm + koff + (uint32_t)(16 * HROW * 2));
#pragma unroll
            for (int mt = 0; mt < 4; mt++)
#pragma unroll
                for (int nt = 0; nt < 4; nt++)
                    mma_f16(acc[mt][nt], af[mt], bf[nt]);
        }
        __syncthreads();
        if (it + 2 < NT) HISSUE(it + 2, s);
        CP_COMMIT();                       // empty group at tail keeps count exact
    }

#pragma unroll
    for (int mt = 0; mt < 4; mt++) {
#pragma unroll
        for (int nt = 0; nt < 4; nt++) {
            const int row = bm + warp_m * 64 + mt * 16 + g;
            const int col = bn + warp_n * 32 + nt * 8 + tg * 2;
            float v0 = acc[mt][nt][0], v1 = acc[mt][nt][1];
            float v2 = acc[mt][nt][2], v3 = acc[mt][nt][3];
            const float b0 = bias[col], b1 = bias[col + 1];
            v0 += b0; v1 += b1; v2 += b0; v3 += b1;
            if (RELU) {
                v0 = fmaxf(v0, 0.f); v1 = fmaxf(v1, 0.f);
                v2 = fmaxf(v2, 0.f); v3 = fmaxf(v3, 0.f);
            }
            if (HASRES) {
                const float* r0p = res + (size_t)row * N + col;
                const float* r1p = res + (size_t)(row + 8) * N + col;
                v0 += r0p[0]; v1 += r0p[1];
                v2 += r1p[0]; v3 += r1p[1];
            }
            if (WRITEH) {
                *(__half2*)(Ch + (size_t)row * N + col) = __floats2half2_rn(v0, v1);
                *(__half2*)(Ch + (size_t)(row + 8) * N + col) = __floats2half2_rn(v2, v3);
            } else {
                *(float2*)(C + (size_t)row * N + col) = make_float2(v0, v1);
                *(float2*)(C + (size_t)(row + 8) * N + col) = make_float2(v2, v3);
            }
        }
    }
#undef HISSUE
}

// ---------------------------------------------------------------------------
// fp16 tensor-core causal flash attention (m16n8k16), 128-query tiles.
// Block: 256 threads (8 warps), one (b,h), 128-query tile; warp = 16 q rows.
// Q resident in registers; K via LDS fragments; V via ldmatrix.x4.trans.
// ---------------------------------------------------------------------------
__global__ __launch_bounds__(256, 2) void attn_h_kernel(
    const __half* __restrict__ qkv, __half* __restrict__ out)
{
    __shared__ __align__(16) __half Qs[128][72];
    __shared__ __align__(16) __half Ks[64][72];
    __shared__ __align__(16) __half Vs[64][72];

    const int tid = threadIdx.x, wid = tid >> 5, lane = tid & 31;
    const int g = lane >> 2, tg = lane & 3;
    const int qt = gridDim.x - 1 - blockIdx.x;     // longest tiles first
    const int bh = blockIdx.y;
    const int b = bh >> 4, h = bh & 15;
    const int qbase = qt * 128;
    const int wr = wid * 16;

    const uint32_t sQ = smem_u32(&Qs[0][0]);
    const uint32_t sK = smem_u32(&Ks[0][0]);
    const uint32_t sV = smem_u32(&Vs[0][0]);

    // ---- stage Q tile (128 x 64 halves), build fragments ----
    for (int i = tid; i < 128 * 8; i += 256) {
        int row = i >> 3, c8 = i & 7;
        cp16(sQ + (uint32_t)(row * 144 + c8 * 16),
             qkv + (size_t)(b * TT + qbase + row) * 3 * DD + h * HSZ + c8 * 8);
    }
    CP_COMMIT(); CP_WAIT(0);
    __syncthreads();

    const __half2 qsc = __float2half2_rn(0.125f);
    uint32_t qa[4][4];
#pragma unroll
    for (int kk = 0; kk < 4; kk++) {
        __half2 v0 = __hmul2(*(__half2*)&Qs[wr + g][kk * 16 + 2 * tg], qsc);
        __half2 v1 = __hmul2(*(__half2*)&Qs[wr + g + 8][kk * 16 + 2 * tg], qsc);
        __half2 v2 = __hmul2(*(__half2*)&Qs[wr + g][kk * 16 + 2 * tg + 8], qsc);
        __half2 v3 = __hmul2(*(__half2*)&Qs[wr + g + 8][kk * 16 + 2 * tg + 8], qsc);
        qa[kk][0] = *(uint32_t*)&v0; qa[kk][1] = *(uint32_t*)&v1;
        qa[kk][2] = *(uint32_t*)&v2; qa[kk][3] = *(uint32_t*)&v3;
    }
    __syncthreads();

    // ldmatrix lane base address into Vs
    const int lrow = lane & 7;
    const int ksel = (lane >> 3) & 1;      // k rows 0-7 vs 8-15 (j offset +8)
    const int dsel = lane >> 4;            // d cols 0-7 vs 8-15 (+16 B)
    const uint32_t vbase = sV + (uint32_t)((ksel * 8 + lrow) * 144 + dsel * 16);

    float o[8][4] = {};
    float m0 = -1e30f, m1 = -1e30f, l0 = 0.0f, l1 = 0.0f;

    const int nchunks = 2 * qt + 2;
    for (int c = 0; c < nchunks; c++) {
        // ---- load K,V chunk (64 x 64 halves each) ----
        for (int i = tid; i < 64 * 8; i += 256) {
            int row = i >> 3, c8 = i & 7;
            const __half* base = qkv + (size_t)(b * TT + c * 64 + row) * 3 * DD + DD + h * HSZ + c8 * 8;
            cp16(sK + (uint32_t)(row * 144 + c8 * 16), base);
            cp16(sV + (uint32_t)(row * 144 + c8 * 16), base + DD);
        }
        CP_COMMIT(); CP_WAIT(0);
        __syncthreads();

        // ---- S = Q K^T ----
        float s[8][4];
#pragma unroll
        for (int nt = 0; nt < 8; nt++) {
            s[nt][0] = 0.f; s[nt][1] = 0.f; s[nt][2] = 0.f; s[nt][3] = 0.f;
            const int j = nt * 8 + g;
#pragma unroll
            for (int kk = 0; kk < 4; kk++) {
                uint32_t bfr[2];
                bfr[0] = *(const uint32_t*)&Ks[j][kk * 16 + 2 * tg];
                bfr[1] = *(const uint32_t*)&Ks[j][kk * 16 + 2 * tg + 8];
                mma_f16(s[nt], qa[kk], bfr);
            }
        }

        // ---- causal mask (only the last two chunks can cross the diagonal) ----
        if (c >= 2 * qt) {
            const int r0 = qbase + wr + g, r1 = r0 + 8;
            const int cb = c * 64;
#pragma unroll
            for (int nt = 0; nt < 8; nt++) {
                const int c0i = cb + nt * 8 + 2 * tg, c1i = c0i + 1;
                if (c0i > r0) s[nt][0] = -1e30f;
                if (c1i > r0) s[nt][1] = -1e30f;
                if (c0i > r1) s[nt][2] = -1e30f;
                if (c1i > r1) s[nt][3] = -1e30f;
            }
        }

        // ---- online softmax ----
        float mx0 = -1e30f, mx1 = -1e30f;
#pragma unroll
        for (int nt = 0; nt < 8; nt++) {
            mx0 = fmaxf(mx0, fmaxf(s[nt][0], s[nt][1]));
            mx1 = fmaxf(mx1, fmaxf(s[nt][2], s[nt][3]));
        }
        mx0 = fmaxf(mx0, __shfl_xor_sync(0xFFFFFFFFu, mx0, 1));
        mx0 = fmaxf(mx0, __shfl_xor_sync(0xFFFFFFFFu, mx0, 2));
        mx1 = fmaxf(mx1, __shfl_xor_sync(0xFFFFFFFFu, mx1, 1));
        mx1 = fmaxf(mx1, __shfl_xor_sync(0xFFFFFFFFu, mx1, 2));

        const float mn0 = fmaxf(m0, mx0), mn1 = fmaxf(m1, mx1);
        const float a0 = __expf(m0 - mn0), a1 = __expf(m1 - mn1);
        float sum0 = 0.f, sum1 = 0.f;
#pragma unroll
        for (int nt = 0; nt < 8; nt++) {
            s[nt][0] = __expf(s[nt][0] - mn0);
            s[nt][1] = __expf(s[nt][1] - mn0);
            s[nt][2] = __expf(s[nt][2] - mn1);
            s[nt][3] = __expf(s[nt][3] - mn1);
            sum0 += s[nt][0] + s[nt][1];
            sum1 += s[nt][2] + s[nt][3];
        }
        sum0 += __shfl_xor_sync(0xFFFFFFFFu, sum0, 1);
        sum0 += __shfl_xor_sync(0xFFFFFFFFu, sum0, 2);
        sum1 += __shfl_xor_sync(0xFFFFFFFFu, sum1, 1);
        sum1 += __shfl_xor_sync(0xFFFFFFFFu, sum1, 2);
        l0 = l0 * a0 + sum0;
        l1 = l1 * a1 + sum1;
        m0 = mn0; m1 = mn1;

#pragma unroll
        for (int dt = 0; dt < 8; dt++) {
            o[dt][0] *= a0; o[dt][1] *= a0;
            o[dt][2] *= a1; o[dt][3] *= a1;
        }

        // ---- O += P V (P fragments come straight from S accumulators) ----
#pragma unroll
        for (int js = 0; js < 4; js++) {
            uint32_t pa[4];
            pa[0] = packh2(s[2 * js][0], s[2 * js][1]);
            pa[1] = packh2(s[2 * js][2], s[2 * js][3]);
            pa[2] = packh2(s[2 * js + 1][0], s[2 * js + 1][1]);
            pa[3] = packh2(s[2 * js + 1][2], s[2 * js + 1][3]);
            const uint32_t vrow = vbase + (uint32_t)(js * 16 * 144);
#pragma unroll
            for (int dt = 0; dt < 4; dt++) {
                uint32_t r0, r1, r2, r3;
                ldmx4t(r0, r1, r2, r3, vrow + (uint32_t)(dt * 32));
                uint32_t bA[2] = { r0, r1 };
                uint32_t bB[2] = { r2, r3 };
                mma_f16(o[dt * 2], pa, bA);
                mma_f16(o[dt * 2 + 1], pa, bB);
            }
        }
        __syncthreads();
    }

    // ---- epilogue: O / l -> fp16 out ----
    const float inv0 = 1.0f / l0, inv1 = 1.0f / l1;
    const int row0 = b * TT + qbase + wr + g;
#pragma unroll
    for (int dt = 0; dt < 8; dt++) {
        const int col = h * HSZ + dt * 8 + 2 * tg;
        *(__half2*)(out + (size_t)row0 * DD + col) =
            __floats2half2_rn(o[dt][0] * inv0, o[dt][1] * inv0);
        *(__half2*)(out + (size_t)(row0 + 8) * DD + col) =
            __floats2half2_rn(o[dt][2] * inv1, o[dt][3] * inv1);
    }
}

// ---------------------------------------------------------------------------
// LayerNorm over last dim (1024). WH=1: also write fp16 copy.
// ---------------------------------------------------------------------------
template <int WH>
__global__ __launch_bounds__(256) void ln_kernel(
    const float* __restrict__ in, const float* __restrict__ g,
    const float* __restrict__ be, float* __restrict__ out,
    __half* __restrict__ outh)
{
    int row = blockIdx.x;
    int tid = threadIdx.x;
    const float* x = in + (size_t)row * DD;

    float4 v = *(const float4*)(x + tid * 4);
    float s = v.x + v.y + v.z + v.w;
    float ss = v.x * v.x + v.y * v.y + v.z * v.z + v.w * v.w;

    __shared__ float red[2][8];
#pragma unroll
    for (int off = 16; off > 0; off >>= 1) {
        s += __shfl_xor_sync(0xFFFFFFFFu, s, off);
        ss += __shfl_xor_sync(0xFFFFFFFFu, ss, off);
    }
    int w = tid >> 5;
    if ((tid & 31) == 0) { red[0][w] = s; red[1][w] = ss; }
    __syncthreads();
    float S = 0.f, SS = 0.f;
#pragma unroll
    for (int i = 0; i < 8; i++) { S += red[0][i]; SS += red[1][i]; }

    float mu = S * (1.0f / DD);
    float var = SS * (1.0f / DD) - mu * mu;
    float rinv = rsqrtf(var + 1e-5f);

    float4 gv = *(const float4*)(g + tid * 4);
    float4 bv = *(const float4*)(be + tid * 4);
    float4 ov;
    ov.x = (v.x - mu) * rinv * gv.x + bv.x;
    ov.y = (v.y - mu) * rinv * gv.y + bv.y;
    ov.z = (v.z - mu) * rinv * gv.z + bv.z;
    ov.w = (v.w - mu) * rinv * gv.w + bv.w;
    *(float4*)(out + (size_t)row * DD + tid * 4) = ov;
    if (WH) {
        __half2 h[2];
        h[0] = __floats2half2_rn(ov.x, ov.y);
        h[1] = __floats2half2_rn(ov.z, ov.w);
        *(float2*)(outh + (size_t)row * DD + tid * 4) = *(float2*)h;
    }
}

// ---------------------------------------------------------------------------
// Launch (kernel launches only — no attribute calls, no dynamic smem)
// ---------------------------------------------------------------------------
extern "C" void kernel_launch(void* const* d_in, const int* in_sizes, int n_in,
                              void* d_out, int out_size)
{
    const float* x      = (const float*)d_in[0];
    const float* w_qkv  = (const float*)d_in[1];
    const float* b_qkv  = (const float*)d_in[2];
    const float* w_fc   = (const float*)d_in[3];
    const float* b_fc   = (const float*)d_in[4];
    const float* g1     = (const float*)d_in[5];
    const float* beta1  = (const float*)d_in[6];
    const float* w_ff1  = (const float*)d_in[7];
    const float* b_ff1  = (const float*)d_in[8];
    const float* w_ff2  = (const float*)d_in[9];
    const float* b_ff2  = (const float*)d_in[10];
    const float* g2     = (const float*)d_in[11];
    const float* beta2  = (const float*)d_in[12];
    float* out = (float*)d_out;

    float *buf, *ln1;
    __half *qkvh, *xh, *atth, *ln1h, *ff1h, *wqkvT, *wfcT, *wff1T, *wff2T;
    cudaGetSymbolAddress((void**)&buf, g_buf);
    cudaGetSymbolAddress((void**)&ln1, g_ln1);
    cudaGetSymbolAddress((void**)&qkvh, g_qkvh);
    cudaGetSymbolAddress((void**)&xh, g_xh);
    cudaGetSymbolAddress((void**)&atth, g_atth);
    cudaGetSymbolAddress((void**)&ln1h, g_ln1h);
    cudaGetSymbolAddress((void**)&ff1h, g_ff1h);
    cudaGetSymbolAddress((void**)&wqkvT, g_wqkvT);
    cudaGetSymbolAddress((void**)&wfcT, g_wfcT);
    cudaGetSymbolAddress((void**)&wff1T, g_wff1T);
    cudaGetSymbolAddress((void**)&wff2T, g_wff2T);

    // 0) convert/transpose weights + x
    wtcvt_kernel<<<dim3(DD/32, 3*DD/32), 256>>>(w_qkv, wqkvT, DD, 3*DD);
    wtcvt_kernel<<<dim3(DD/32, DD/32), 256>>>(w_fc, wfcT, DD, DD);
    wtcvt_kernel<<<dim3(DD/32, FFD/32), 256>>>(w_ff1, wff1T, DD, FFD);
    wtcvt_kernel<<<dim3(FFD/32, DD/32), 256>>>(w_ff2, wff2T, FFD, DD);
    f2h_kernel<<<(MR*DD)/2048, 256>>>(x, xh);

    // 1) qkvh = fp16(x @ w_qkv + b_qkv)         [4096, 3072]
    hgemm<0,0,1><<<dim3(3*DD/128, MR/128), 256>>>(
        xh, wqkvT, b_qkv, nullptr, nullptr, qkvh, MR, 3*DD, DD);

    // 2) attention (fp16 mma, 128-q tiles) -> fp16 att
    attn_h_kernel<<<dim3(TT/128, BB*HH), 256>>>(qkvh, atth);

    // 3) buf = att @ w_fc + b_fc + x (residual fused) fp32
    hgemm<0,1,0><<<dim3(DD/128, MR/128), 256>>>(
        atth, wfcT, b_fc, x, buf, nullptr, MR, DD, DD);

    // 4) ln1 = LN(buf) -> fp32 + fp16
    ln_kernel<1><<<MR, 256>>>(buf, g1, beta1, ln1, ln1h);

    // 5) ff1h = relu(ln1 @ w_ff1 + b_ff1) fp16 only
    hgemm<1,0,1><<<dim3(FFD/128, MR/128), 256>>>(
        ln1h, wff1T, b_ff1, nullptr, nullptr, ff1h, MR, FFD, DD);

    // 6) buf = ff1 @ w_ff2 + b_ff2 + ln1 (residual fused, no split-K)
    hgemm<0,1,0><<<dim3(DD/128, MR/128), 256>>>(
        ff1h, wff2T, b_ff2, ln1, buf, nullptr, MR, DD, FFD);

    // 7) out = LN(buf)
    ln_kernel<0><<<MR, 256>>>(buf, g2, beta2, out, nullptr);
}

// round 14
// speedup vs baseline: 1.0191x; 1.0191x over previous
#include <cuda_runtime.h>
#include <cuda_fp16.h>
#include <math.h>
#include <stdint.h>

// Problem constants
#define BB 2
#define TT 2048
#define DD 1024
#define HH 16
#define HSZ 64
#define FFD 16384
#define MR (BB*TT)          // 4096 rows

// ---------------------------------------------------------------------------
// Scratch (static device globals; no runtime allocation)
// ---------------------------------------------------------------------------
__device__ float g_buf[(size_t)MR * DD];         // 16 MB
__device__ float g_ln1[(size_t)MR * DD];         // 16 MB
__device__ __half g_qkvh[(size_t)MR * 3 * DD];   // 25 MB
__device__ __half g_xh[(size_t)MR * DD];
__device__ __half g_atth[(size_t)MR * DD];
__device__ __half g_ln1h[(size_t)MR * DD];
__device__ __half g_ff1h[(size_t)MR * FFD];      // 128 MB
__device__ __half g_wqkvT[(size_t)3 * DD * DD];
__device__ __half g_wfcT[(size_t)DD * DD];
__device__ __half g_wff1T[(size_t)FFD * DD];
__device__ __half g_wff2T[(size_t)DD * FFD];

// ---------------------------------------------------------------------------
// PTX helpers (plain sm_100 legal: mma.sync + cp.async + ldmatrix only)
// ---------------------------------------------------------------------------
__device__ __forceinline__ uint32_t smem_u32(const void* p) {
    uint32_t a;
    asm("{ .reg .u64 t; cvta.to.shared.u64 t, %1; cvt.u32.u64 %0, t; }" : "=r"(a) : "l"(p));
    return a;
}
__device__ __forceinline__ void cp16(uint32_t dst, const void* src) {
    asm volatile("cp.async.cg.shared.global [%0], [%1], 16;" :: "r"(dst), "l"(src) : "memory");
}
#define CP_COMMIT() asm volatile("cp.async.commit_group;" ::: "memory")
#define CP_WAIT(n)  asm volatile("cp.async.wait_group %0;" :: "n"(n) : "memory")

__device__ __forceinline__ void mma_f16(float* c, const uint32_t* a, const uint32_t* b) {
    asm volatile("mma.sync.aligned.m16n8k16.row.col.f32.f16.f16.f32 "
        "{%0,%1,%2,%3}, {%4,%5,%6,%7}, {%8,%9}, {%0,%1,%2,%3};"
        : "+f"(c[0]), "+f"(c[1]), "+f"(c[2]), "+f"(c[3])
        : "r"(a[0]), "r"(a[1]), "r"(a[2]), "r"(a[3]), "r"(b[0]), "r"(b[1]));
}
__device__ __forceinline__ void ldmx4(uint32_t& r0, uint32_t& r1, uint32_t& r2, uint32_t& r3,
                                      uint32_t addr) {
    asm volatile("ldmatrix.sync.aligned.m8n8.x4.shared.b16 {%0,%1,%2,%3}, [%4];"
        : "=r"(r0), "=r"(r1), "=r"(r2), "=r"(r3) : "r"(addr));
}
__device__ __forceinline__ void ldmx4t(uint32_t& r0, uint32_t& r1, uint32_t& r2, uint32_t& r3,
                                       uint32_t addr) {
    asm volatile("ldmatrix.sync.aligned.m8n8.x4.trans.shared.b16 {%0,%1,%2,%3}, [%4];"
        : "=r"(r0), "=r"(r1), "=r"(r2), "=r"(r3) : "r"(addr));
}
__device__ __forceinline__ uint32_t packh2(float a, float b) {
    __half2 h = __floats2half2_rn(a, b);
    return *(uint32_t*)&h;
}

// ---------------------------------------------------------------------------
// Weight convert + transpose: Wt[n][k] = (half)W[k][n]
// Tile 64(K) x 32(N); 16B vectorized stores (128B per warp-row).
// ---------------------------------------------------------------------------
__global__ __launch_bounds__(256) void wtcvt_kernel(
    const float* __restrict__ W, __half* __restrict__ Wt, int K, int N)
{
    __shared__ float t[64][33];
    const int k0 = blockIdx.x * 64, n0 = blockIdx.y * 32;
    const int tx = threadIdx.x & 31, ty = threadIdx.x >> 5;   // 32 x 8
#pragma unroll
    for (int i = 0; i < 8; i++)
        t[ty + 8 * i][tx] = W[(size_t)(k0 + ty + 8 * i) * N + n0 + tx];
    __syncthreads();
    const int r = threadIdx.x >> 3;           // 0..31 (n-row within tile)
    const int cg = (threadIdx.x & 7) * 8;     // 0..56 (k-col group of 8)
    __half2 h[4];
#pragma unroll
    for (int j = 0; j < 4; j++)
        h[j] = __floats2half2_rn(t[cg + 2 * j][r], t[cg + 2 * j + 1][r]);
    *(float4*)(Wt + (size_t)(n0 + r) * K + k0 + cg) = *(float4*)h;
}

// x fp32 -> fp16 (8 elements per thread)
__global__ __launch_bounds__(256) void f2h_kernel(
    const float* __restrict__ in, __half* __restrict__ out)
{
    size_t i = ((size_t)blockIdx.x * 256 + threadIdx.x) * 8;
    float4 a = *(const float4*)(in + i);
    float4 b = *(const float4*)(in + i + 4);
    __half2 h[4];
    h[0] = __floats2half2_rn(a.x, a.y);
    h[1] = __floats2half2_rn(a.z, a.w);
    h[2] = __floats2half2_rn(b.x, b.y);
    h[3] = __floats2half2_rn(b.z, b.w);
    *(float4*)(out + i) = *(float4*)h;
}

// ---------------------------------------------------------------------------
// fp16 tensor-core GEMM: C[M,N] = A[M,K] @ Wt^T (Wt is [N,K] fp16)
// BM=BN=128, BK=32, 256 threads (8 warps 2x4), warp tile 64x32.
// 2-stage cp.async ring, static smem, ldmatrix.x4 fragment loads.
// WRITEH: write fp16 to Ch instead of fp32 to C.   [R12-identical]
// ---------------------------------------------------------------------------
#define HROW 40                       // halves per smem row (32 + 8 pad)
#define ASTGB (128 * HROW * 2)        // 10240 B per operand stage
#define SSTGB (2 * ASTGB)             // 20480 B per stage (A+B)

template <int RELU, int HASRES, int WRITEH>
__global__ __launch_bounds__(256, 2) void hgemm(
    const __half* __restrict__ A, const __half* __restrict__ Bt,
    const float* __restrict__ bias, const float* __restrict__ res,
    float* __restrict__ C, __half* __restrict__ Ch, int M, int N, int Kt)
{
    __shared__ __half hs[2 * SSTGB / 2];     // 2 stages x 20480 B

    const int tid = threadIdx.x;
    const int wid = tid >> 5, lane = tid & 31;
    const int g = lane >> 2, tg = lane & 3;
    const int warp_m = wid & 1, warp_n = wid >> 1;
    const int bm = blockIdx.y * 128, bn = blockIdx.x * 128;
    const int NT = Kt / 32;
    const uint32_t sb = smem_u32(hs);

    // ldmatrix per-lane addresses (bytes, stage 0, kk 0)
    const int li = lane >> 3, lr = lane & 7;
    // A x4: m0=(r0,k0) m1=(r0+8,k0) m2=(r0,k8) m3=(r0+8,k8)
    const uint32_t a_lm = sb +
        (uint32_t)(((warp_m * 64 + (li & 1) * 8 + lr) * HROW + (li >> 1) * 8) * 2);
    // B x4: m0=(n0,k0) m1=(n0,k8) m2=(n0+8,k0) m3=(n0+8,k8)
    const uint32_t b_lm = sb + ASTGB +
        (uint32_t)(((warp_n * 32 + (li >> 1) * 8 + lr) * HROW + (li & 1) * 8) * 2);

    float acc[4][4][4] = {};

    const int c_row = tid >> 1;            // 0..127
    const int c_ch0 = (tid & 1) * 2;       // chunk base {0,2}; 16B chunks

#define HISSUE(it, s) do { \
        const int k0 = (it) * 32; \
        const uint32_t so = (uint32_t)(s) * SSTGB + (uint32_t)c_row * 80 + (uint32_t)c_ch0 * 16; \
        const __half* ag = A  + (size_t)(bm + c_row) * Kt + k0 + c_ch0 * 8; \
        const __half* bg = Bt + (size_t)(bn + c_row) * Kt + k0 + c_ch0 * 8; \
        cp16(sb + so,              ag); \
        cp16(sb + so + 16,         ag + 8); \
        cp16(sb + ASTGB + so,      bg); \
        cp16(sb + ASTGB + so + 16, bg + 8); \
    } while (0)

    HISSUE(0, 0); CP_COMMIT();
    HISSUE(1, 1); CP_COMMIT();

    for (int it = 0; it < NT; it++) {
        const int s = it & 1;
        CP_WAIT(1);
        __syncthreads();

        const uint32_t soff = (uint32_t)s * SSTGB;

#pragma unroll
        for (int kk = 0; kk < 2; kk++) {
            const uint32_t koff = soff + (uint32_t)kk * 32;   // 16 halves = 32 B
            uint32_t af[4][4], bf[4][2];
#pragma unroll
            for (int mt = 0; mt < 4; mt++)
                ldmx4(af[mt][0], af[mt][1], af[mt][2], af[mt][3],
                      a_lm + koff + (uint32_t)(mt * 16 * HROW * 2));
            ldmx4(bf[0][0], bf[0][1], bf[1][0], bf[1][1], b_lm + koff);
            ldmx4(bf[2][0], bf[2][1], bf[3][0], bf[3][1],
                  b_lm + koff + (uint32_t)(16 * HROW * 2));
#pragma unroll
            for (int mt = 0; mt < 4; mt++)
#pragma unroll
                for (int nt = 0; nt < 4; nt++)
                    mma_f16(acc[mt][nt], af[mt], bf[nt]);
        }
        __syncthreads();
        if (it + 2 < NT) HISSUE(it + 2, s);
        CP_COMMIT();                       // empty group at tail keeps count exact
    }

#pragma unroll
    for (int mt = 0; mt < 4; mt++) {
#pragma unroll
        for (int nt = 0; nt < 4; nt++) {
            const int row = bm + warp_m * 64 + mt * 16 + g;
            const int col = bn + warp_n * 32 + nt * 8 + tg * 2;
            float v0 = acc[mt][nt][0], v1 = acc[mt][nt][1];
            float v2 = acc[mt][nt][2], v3 = acc[mt][nt][3];
            const float b0 = bias[col], b1 = bias[col + 1];
            v0 += b0; v1 += b1; v2 += b0; v3 += b1;
            if (RELU) {
                v0 = fmaxf(v0, 0.f); v1 = fmaxf(v1, 0.f);
                v2 = fmaxf(v2, 0.f); v3 = fmaxf(v3, 0.f);
            }
            if (HASRES) {
                const float* r0p = res + (size_t)row * N + col;
                const float* r1p = res + (size_t)(row + 8) * N + col;
                v0 += r0p[0]; v1 += r0p[1];
                v2 += r1p[0]; v3 += r1p[1];
            }
            if (WRITEH) {
                *(__half2*)(Ch + (size_t)row * N + col) = __floats2half2_rn(v0, v1);
                *(__half2*)(Ch + (size_t)(row + 8) * N + col) = __floats2half2_rn(v2, v3);
            } else {
                *(float2*)(C + (size_t)row * N + col) = make_float2(v0, v1);
                *(float2*)(C + (size_t)(row + 8) * N + col) = make_float2(v2, v3);
            }
        }
    }
#undef HISSUE
}

// ---------------------------------------------------------------------------
// fp16 tensor-core causal flash attention (m16n8k16).  [R12-identical]
// Block: 128 threads (4 warps), one (b,h), 64-query tile; warp = 16 q rows.
// S accum layout == P A-operand layout (no shuffles); V via ldmatrix.x4.trans.
// ---------------------------------------------------------------------------
__global__ __launch_bounds__(128, 3) void attn_h_kernel(
    const __half* __restrict__ qkv, __half* __restrict__ out)
{
    __shared__ __align__(16) __half Ks[64][72];
    __shared__ __align__(16) __half Vs[64][72];

    const int tid = threadIdx.x, wid = tid >> 5, lane = tid & 31;
    const int g = lane >> 2, tg = lane & 3;
    const int qt = gridDim.x - 1 - blockIdx.x;     // longest tiles first
    const int bh = blockIdx.y;
    const int b = bh >> 4, h = bh & 15;
    const int qbase = qt * 64;
    const int wr = wid * 16;

    const uint32_t sK = smem_u32(&Ks[0][0]);
    const uint32_t sV = smem_u32(&Vs[0][0]);

    // ---- stage Q tile (64 x 64 halves) through Ks, build fragments ----
    for (int i = tid; i < 64 * 8; i += 128) {
        int row = i >> 3, c8 = i & 7;
        cp16(sK + (uint32_t)(row * 144 + c8 * 16),
             qkv + (size_t)(b * TT + qbase + row) * 3 * DD + h * HSZ + c8 * 8);
    }
    CP_COMMIT(); CP_WAIT(0);
    __syncthreads();

    const __half2 qsc = __float2half2_rn(0.125f);
    uint32_t qa[4][4];
#pragma unroll
    for (int kk = 0; kk < 4; kk++) {
        __half2 v0 = __hmul2(*(__half2*)&Ks[wr + g][kk * 16 + 2 * tg], qsc);
        __half2 v1 = __hmul2(*(__half2*)&Ks[wr + g + 8][kk * 16 + 2 * tg], qsc);
        __half2 v2 = __hmul2(*(__half2*)&Ks[wr + g][kk * 16 + 2 * tg + 8], qsc);
        __half2 v3 = __hmul2(*(__half2*)&Ks[wr + g + 8][kk * 16 + 2 * tg + 8], qsc);
        qa[kk][0] = *(uint32_t*)&v0; qa[kk][1] = *(uint32_t*)&v1;
        qa[kk][2] = *(uint32_t*)&v2; qa[kk][3] = *(uint32_t*)&v3;
    }
    __syncthreads();

    // ldmatrix lane base address into Vs
    const int lrow = lane & 7;
    const int ksel = (lane >> 3) & 1;      // k rows 0-7 vs 8-15 (j offset +8)
    const int dsel = lane >> 4;            // d cols 0-7 vs 8-15 (+16 B)
    const uint32_t vbase = sV + (uint32_t)((ksel * 8 + lrow) * 144 + dsel * 16);

    float o[8][4] = {};
    float m0 = -1e30f, m1 = -1e30f, l0 = 0.0f, l1 = 0.0f;

    const int nchunks = qt + 1;
    for (int c = 0; c < nchunks; c++) {
        // ---- load K,V chunk (64 x 64 halves each) ----
        for (int i = tid; i < 64 * 8; i += 128) {
            int row = i >> 3, c8 = i & 7;
            const __half* base = qkv + (size_t)(b * TT + c * 64 + row) * 3 * DD + DD + h * HSZ + c8 * 8;
            cp16(sK + (uint32_t)(row * 144 + c8 * 16), base);
            cp16(sV + (uint32_t)(row * 144 + c8 * 16), base + DD);
        }
        CP_COMMIT(); CP_WAIT(0);
        __syncthreads();

        // ---- S = Q K^T ----
        float s[8][4];
#pragma unroll
        for (int nt = 0; nt < 8; nt++) {
            s[nt][0] = 0.f; s[nt][1] = 0.f; s[nt][2] = 0.f; s[nt][3] = 0.f;
            const int j = nt * 8 + g;
#pragma unroll
            for (int kk = 0; kk < 4; kk++) {
                uint32_t bfr[2];
                bfr[0] = *(const uint32_t*)&Ks[j][kk * 16 + 2 * tg];
                bfr[1] = *(const uint32_t*)&Ks[j][kk * 16 + 2 * tg + 8];
                mma_f16(s[nt], qa[kk], bfr);
            }
        }

        // ---- causal mask on diagonal chunk ----
        if (c == qt) {
            const int r0 = wr + g, r1 = wr + g + 8;
#pragma unroll
            for (int nt = 0; nt < 8; nt++) {
                const int c0i = nt * 8 + 2 * tg, c1i = c0i + 1;
                if (c0i > r0) s[nt][0] = -1e30f;
                if (c1i > r0) s[nt][1] = -1e30f;
                if (c0i > r1) s[nt][2] = -1e30f;
                if (c1i > r1) s[nt][3] = -1e30f;
            }
        }

        // ---- online softmax ----
        float mx0 = -1e30f, mx1 = -1e30f;
#pragma unroll
        for (int nt = 0; nt < 8; nt++) {
            mx0 = fmaxf(mx0, fmaxf(s[nt][0], s[nt][1]));
            mx1 = fmaxf(mx1, fmaxf(s[nt][2], s[nt][3]));
        }
        mx0 = fmaxf(mx0, __shfl_xor_sync(0xFFFFFFFFu, mx0, 1));
        mx0 = fmaxf(mx0, __shfl_xor_sync(0xFFFFFFFFu, mx0, 2));
        mx1 = fmaxf(mx1, __shfl_xor_sync(0xFFFFFFFFu, mx1, 1));
        mx1 = fmaxf(mx1, __shfl_xor_sync(0xFFFFFFFFu, mx1, 2));

        const float mn0 = fmaxf(m0, mx0), mn1 = fmaxf(m1, mx1);
        const float a0 = __expf(m0 - mn0), a1 = __expf(m1 - mn1);
        float sum0 = 0.f, sum1 = 0.f;
#pragma unroll
        for (int nt = 0; nt < 8; nt++) {
            s[nt][0] = __expf(s[nt][0] - mn0);
            s[nt][1] = __expf(s[nt][1] - mn0);
            s[nt][2] = __expf(s[nt][2] - mn1);
            s[nt][3] = __expf(s[nt][3] - mn1);
            sum0 += s[nt][0] + s[nt][1];
            sum1 += s[nt][2] + s[nt][3];
        }
        sum0 += __shfl_xor_sync(0xFFFFFFFFu, sum0, 1);
        sum0 += __shfl_xor_sync(0xFFFFFFFFu, sum0, 2);
        sum1 += __shfl_xor_sync(0xFFFFFFFFu, sum1, 1);
        sum1 += __shfl_xor_sync(0xFFFFFFFFu, sum1, 2);
        l0 = l0 * a0 + sum0;
        l1 = l1 * a1 + sum1;
        m0 = mn0; m1 = mn1;

#pragma unroll
        for (int dt = 0; dt < 8; dt++) {
            o[dt][0] *= a0; o[dt][1] *= a0;
            o[dt][2] *= a1; o[dt][3] *= a1;
        }

        // ---- O += P V (P fragments come straight from S accumulators) ----
#pragma unroll
        for (int js = 0; js < 4; js++) {
            uint32_t pa[4];
            pa[0] = packh2(s[2 * js][0], s[2 * js][1]);
            pa[1] = packh2(s[2 * js][2], s[2 * js][3]);
            pa[2] = packh2(s[2 * js + 1][0], s[2 * js + 1][1]);
            pa[3] = packh2(s[2 * js + 1][2], s[2 * js + 1][3]);
            const uint32_t vrow = vbase + (uint32_t)(js * 16 * 144);
#pragma unroll
            for (int dt = 0; dt < 4; dt++) {
                uint32_t r0, r1, r2, r3;
                ldmx4t(r0, r1, r2, r3, vrow + (uint32_t)(dt * 32));
                uint32_t bA[2] = { r0, r1 };
                uint32_t bB[2] = { r2, r3 };
                mma_f16(o[dt * 2], pa, bA);
                mma_f16(o[dt * 2 + 1], pa, bB);
            }
        }
        __syncthreads();
    }

    // ---- epilogue: O / l -> fp16 out ----
    const float inv0 = 1.0f / l0, inv1 = 1.0f / l1;
    const int row0 = b * TT + qbase + wr + g;
#pragma unroll
    for (int dt = 0; dt < 8; dt++) {
        const int col = h * HSZ + dt * 8 + 2 * tg;
        *(__half2*)(out + (size_t)row0 * DD + col) =
            __floats2half2_rn(o[dt][0] * inv0, o[dt][1] * inv0);
        *(__half2*)(out + (size_t)(row0 + 8) * DD + col) =
            __floats2half2_rn(o[dt][2] * inv1, o[dt][3] * inv1);
    }
}

// ---------------------------------------------------------------------------
// LayerNorm over last dim (1024). WH=1: also write fp16 copy.
// ---------------------------------------------------------------------------
template <int WH>
__global__ __launch_bounds__(256) void ln_kernel(
    const float* __restrict__ in, const float* __restrict__ g,
    const float* __restrict__ be, float* __restrict__ out,
    __half* __restrict__ outh)
{
    int row = blockIdx.x;
    int tid = threadIdx.x;
    const float* x = in + (size_t)row * DD;

    float4 v = *(const float4*)(x + tid * 4);
    float s = v.x + v.y + v.z + v.w;
    float ss = v.x * v.x + v.y * v.y + v.z * v.z + v.w * v.w;

    __shared__ float red[2][8];
#pragma unroll
    for (int off = 16; off > 0; off >>= 1) {
        s += __shfl_xor_sync(0xFFFFFFFFu, s, off);
        ss += __shfl_xor_sync(0xFFFFFFFFu, ss, off);
    }
    int w = tid >> 5;
    if ((tid & 31) == 0) { red[0][w] = s; red[1][w] = ss; }
    __syncthreads();
    float S = 0.f, SS = 0.f;
#pragma unroll
    for (int i = 0; i < 8; i++) { S += red[0][i]; SS += red[1][i]; }

    float mu = S * (1.0f / DD);
    float var = SS * (1.0f / DD) - mu * mu;
    float rinv = rsqrtf(var + 1e-5f);

    float4 gv = *(const float4*)(g + tid * 4);
    float4 bv = *(const float4*)(be + tid * 4);
    float4 ov;
    ov.x = (v.x - mu) * rinv * gv.x + bv.x;
    ov.y = (v.y - mu) * rinv * gv.y + bv.y;
    ov.z = (v.z - mu) * rinv * gv.z + bv.z;
    ov.w = (v.w - mu) * rinv * gv.w + bv.w;
    *(float4*)(out + (size_t)row * DD + tid * 4) = ov;
    if (WH) {
        __half2 h[2];
        h[0] = __floats2half2_rn(ov.x, ov.y);
        h[1] = __floats2half2_rn(ov.z, ov.w);
        *(float2*)(outh + (size_t)row * DD + tid * 4) = *(float2*)h;
    }
}

// ---------------------------------------------------------------------------
// Launch (kernel launches only — no attribute calls, no dynamic smem)
// ---------------------------------------------------------------------------
extern "C" void kernel_launch(void* const* d_in, const int* in_sizes, int n_in,
                              void* d_out, int out_size)
{
    const float* x      = (const float*)d_in[0];
    const float* w_qkv  = (const float*)d_in[1];
    const float* b_qkv  = (const float*)d_in[2];
    const float* w_fc   = (const float*)d_in[3];
    const float* b_fc   = (const float*)d_in[4];
    const float* g1     = (const float*)d_in[5];
    const float* beta1  = (const float*)d_in[6];
    const float* w_ff1  = (const float*)d_in[7];
    const float* b_ff1  = (const float*)d_in[8];
    const float* w_ff2  = (const float*)d_in[9];
    const float* b_ff2  = (const float*)d_in[10];
    const float* g2     = (const float*)d_in[11];
    const float* beta2  = (const float*)d_in[12];
    float* out = (float*)d_out;

    float *buf, *ln1;
    __half *qkvh, *xh, *atth, *ln1h, *ff1h, *wqkvT, *wfcT, *wff1T, *wff2T;
    cudaGetSymbolAddress((void**)&buf, g_buf);
    cudaGetSymbolAddress((void**)&ln1, g_ln1);
    cudaGetSymbolAddress((void**)&qkvh, g_qkvh);
    cudaGetSymbolAddress((void**)&xh, g_xh);
    cudaGetSymbolAddress((void**)&atth, g_atth);
    cudaGetSymbolAddress((void**)&ln1h, g_ln1h);
    cudaGetSymbolAddress((void**)&ff1h, g_ff1h);
    cudaGetSymbolAddress((void**)&wqkvT, g_wqkvT);
    cudaGetSymbolAddress((void**)&wfcT, g_wfcT);
    cudaGetSymbolAddress((void**)&wff1T, g_wff1T);
    cudaGetSymbolAddress((void**)&wff2T, g_wff2T);

    // 0) convert/transpose weights + x (64x32 tiles)
    wtcvt_kernel<<<dim3(DD/64, 3*DD/32), 256>>>(w_qkv, wqkvT, DD, 3*DD);
    wtcvt_kernel<<<dim3(DD/64, DD/32), 256>>>(w_fc, wfcT, DD, DD);
    wtcvt_kernel<<<dim3(DD/64, FFD/32), 256>>>(w_ff1, wff1T, DD, FFD);
    wtcvt_kernel<<<dim3(FFD/64, DD/32), 256>>>(w_ff2, wff2T, FFD, DD);
    f2h_kernel<<<(MR*DD)/2048, 256>>>(x, xh);

    // 1) qkvh = fp16(x @ w_qkv + b_qkv)         [4096, 3072]
    hgemm<0,0,1><<<dim3(3*DD/128, MR/128), 256>>>(
        xh, wqkvT, b_qkv, nullptr, nullptr, qkvh, MR, 3*DD, DD);

    // 2) attention (fp16 mma) -> fp16 att
    attn_h_kernel<<<dim3(TT/64, BB*HH), 128>>>(qkvh, atth);

    // 3) buf = att @ w_fc + b_fc + x (residual fused) fp32
    hgemm<0,1,0><<<dim3(DD/128, MR/128), 256>>>(
        atth, wfcT, b_fc, x, buf, nullptr, MR, DD, DD);

    // 4) ln1 = LN(buf) -> fp32 + fp16
    ln_kernel<1><<<MR, 256>>>(buf, g1, beta1, ln1, ln1h);

    // 5) ff1h = relu(ln1 @ w_ff1 + b_ff1) fp16 only
    hgemm<1,0,1><<<dim3(FFD/128, MR/128), 256>>>(
        ln1h, wff1T, b_ff1, nullptr, nullptr, ff1h, MR, FFD, DD);

    // 6) buf = ff1 @ w_ff2 + b_ff2 + ln1 (residual fused, no split-K)
    hgemm<0,1,0><<<dim3(DD/128, MR/128), 256>>>(
        ff1h, wff2T, b_ff2, ln1, buf, nullptr, MR, DD, FFD);

    // 7) out = LN(buf)
    ln_kernel<0><<<MR, 256>>>(buf, g2, beta2, out, nullptr);
}

// round 15
// speedup vs baseline: 1.0729x; 1.0528x over previous
#include <cuda_runtime.h>
#include <cuda_fp16.h>
#include <math.h>
#include <stdint.h>

// Problem constants
#define BB 2
#define TT 2048
#define DD 1024
#define HH 16
#define HSZ 64
#define FFD 16384
#define MR (BB*TT)          // 4096 rows

// ---------------------------------------------------------------------------
// Scratch (static device globals; no runtime allocation)
// ---------------------------------------------------------------------------
__device__ float g_buf[(size_t)MR * DD];         // 16 MB
__device__ float g_ln1[(size_t)MR * DD];         // 16 MB
__device__ __half g_qkvh[(size_t)MR * 3 * DD];   // 25 MB
__device__ __half g_xh[(size_t)MR * DD];
__device__ __half g_atth[(size_t)MR * DD];
__device__ __half g_ln1h[(size_t)MR * DD];
__device__ __half g_ff1h[(size_t)MR * FFD];      // 128 MB
__device__ __half g_wqkvT[(size_t)3 * DD * DD];
__device__ __half g_wfcT[(size_t)DD * DD];
__device__ __half g_wff1T[(size_t)FFD * DD];
__device__ __half g_wff2T[(size_t)DD * FFD];

// ---------------------------------------------------------------------------
// PTX helpers (plain sm_100 legal: mma.sync + cp.async + ldmatrix only)
// ---------------------------------------------------------------------------
__device__ __forceinline__ uint32_t smem_u32(const void* p) {
    uint32_t a;
    asm("{ .reg .u64 t; cvta.to.shared.u64 t, %1; cvt.u32.u64 %0, t; }" : "=r"(a) : "l"(p));
    return a;
}
__device__ __forceinline__ void cp16(uint32_t dst, const void* src) {
    asm volatile("cp.async.cg.shared.global [%0], [%1], 16;" :: "r"(dst), "l"(src) : "memory");
}
#define CP_COMMIT() asm volatile("cp.async.commit_group;" ::: "memory")
#define CP_WAIT(n)  asm volatile("cp.async.wait_group %0;" :: "n"(n) : "memory")

__device__ __forceinline__ void mma_f16(float* c, const uint32_t* a, const uint32_t* b) {
    asm volatile("mma.sync.aligned.m16n8k16.row.col.f32.f16.f16.f32 "
        "{%0,%1,%2,%3}, {%4,%5,%6,%7}, {%8,%9}, {%0,%1,%2,%3};"
        : "+f"(c[0]), "+f"(c[1]), "+f"(c[2]), "+f"(c[3])
        : "r"(a[0]), "r"(a[1]), "r"(a[2]), "r"(a[3]), "r"(b[0]), "r"(b[1]));
}
__device__ __forceinline__ void ldmx4(uint32_t& r0, uint32_t& r1, uint32_t& r2, uint32_t& r3,
                                      uint32_t addr) {
    asm volatile("ldmatrix.sync.aligned.m8n8.x4.shared.b16 {%0,%1,%2,%3}, [%4];"
        : "=r"(r0), "=r"(r1), "=r"(r2), "=r"(r3) : "r"(addr));
}
__device__ __forceinline__ void ldmx4t(uint32_t& r0, uint32_t& r1, uint32_t& r2, uint32_t& r3,
                                       uint32_t addr) {
    asm volatile("ldmatrix.sync.aligned.m8n8.x4.trans.shared.b16 {%0,%1,%2,%3}, [%4];"
        : "=r"(r0), "=r"(r1), "=r"(r2), "=r"(r3) : "r"(addr));
}
__device__ __forceinline__ uint32_t packh2(float a, float b) {
    __half2 h = __floats2half2_rn(a, b);
    return *(uint32_t*)&h;
}

// ---------------------------------------------------------------------------
// Weight convert + transpose: Wt[n][k] = (half)W[k][n]
// Tile 64(K) x 32(N); 16B vectorized stores. [R14-identical]
// ---------------------------------------------------------------------------
__global__ __launch_bounds__(256) void wtcvt_kernel(
    const float* __restrict__ W, __half* __restrict__ Wt, int K, int N)
{
    __shared__ float t[64][33];
    const int k0 = blockIdx.x * 64, n0 = blockIdx.y * 32;
    const int tx = threadIdx.x & 31, ty = threadIdx.x >> 5;   // 32 x 8
#pragma unroll
    for (int i = 0; i < 8; i++)
        t[ty + 8 * i][tx] = W[(size_t)(k0 + ty + 8 * i) * N + n0 + tx];
    __syncthreads();
    const int r = threadIdx.x >> 3;           // 0..31 (n-row within tile)
    const int cg = (threadIdx.x & 7) * 8;     // 0..56 (k-col group of 8)
    __half2 h[4];
#pragma unroll
    for (int j = 0; j < 4; j++)
        h[j] = __floats2half2_rn(t[cg + 2 * j][r], t[cg + 2 * j + 1][r]);
    *(float4*)(Wt + (size_t)(n0 + r) * K + k0 + cg) = *(float4*)h;
}

// x fp32 -> fp16 (8 elements per thread)
__global__ __launch_bounds__(256) void f2h_kernel(
    const float* __restrict__ in, __half* __restrict__ out)
{
    size_t i = ((size_t)blockIdx.x * 256 + threadIdx.x) * 8;
    float4 a = *(const float4*)(in + i);
    float4 b = *(const float4*)(in + i + 4);
    __half2 h[4];
    h[0] = __floats2half2_rn(a.x, a.y);
    h[1] = __floats2half2_rn(a.z, a.w);
    h[2] = __floats2half2_rn(b.x, b.y);
    h[3] = __floats2half2_rn(b.z, b.w);
    *(float4*)(out + i) = *(float4*)h;
}

// ---------------------------------------------------------------------------
// fp16 tensor-core GEMM: C[M,N] = A[M,K] @ Wt^T (Wt is [N,K] fp16)
// BM=BN=128, BK=32, 256 threads (8 warps 2x4), warp tile 64x32.
// 3-stage cp.async ring, unpadded rows (64 B) + chunk XOR swizzle
// (c ^= (row>>1)&3) applied at store and ldmatrix load. 49152 B static smem.
// WRITEH: write fp16 to Ch instead of fp32 to C.
// ---------------------------------------------------------------------------
#define CSTG 16384                    // bytes per stage (A 8192 + B 8192)

template <int RELU, int HASRES, int WRITEH>
__global__ __launch_bounds__(256, 2) void hgemm(
    const __half* __restrict__ A, const __half* __restrict__ Bt,
    const float* __restrict__ bias, const float* __restrict__ res,
    float* __restrict__ C, __half* __restrict__ Ch, int M, int N, int Kt)
{
    __shared__ __half hs[3 * CSTG / 2];      // 3 stages x 16384 B = 49152 B

    const int tid = threadIdx.x;
    const int wid = tid >> 5, lane = tid & 31;
    const int g = lane >> 2, tg = lane & 3;
    const int warp_m = wid & 1, warp_n = wid >> 1;
    const int bm = blockIdx.y * 128, bn = blockIdx.x * 128;
    const int NT = Kt / 32;
    const uint32_t sb = smem_u32(hs);

    // ldmatrix per-lane mapping (tile order identical to R12; chunk swizzled)
    const int li = lane >> 3, lr = lane & 7;
    const int a_row = warp_m * 64 + (li & 1) * 8 + lr;
    const uint32_t a_ch  = (uint32_t)(li >> 1);
    const uint32_t a_swz = (uint32_t)((a_row >> 1) & 3);
    const uint32_t a_rb  = (uint32_t)(a_row * 64);
    const int b_row = warp_n * 32 + (li >> 1) * 8 + lr;
    const uint32_t b_ch  = (uint32_t)(li & 1);
    const uint32_t b_swz = (uint32_t)((b_row >> 1) & 3);
    const uint32_t b_rb  = (uint32_t)(b_row * 64) + 8192;

    float acc[4][4][4] = {};

    const int c_row = tid >> 1;            // 0..127
    const int c_ch0 = (tid & 1) * 2;       // chunk base {0,2}; 16B chunks
    const uint32_t st_swz = (uint32_t)((c_row >> 1) & 3);
    const uint32_t st_rb  = (uint32_t)(c_row * 64);

#define HISSUE(it, s) do { \
        const int k0 = (it) * 32; \
        const uint32_t so = (uint32_t)(s) * CSTG + st_rb; \
        const __half* ag = A  + (size_t)(bm + c_row) * Kt + k0 + c_ch0 * 8; \
        const __half* bg = Bt + (size_t)(bn + c_row) * Kt + k0 + c_ch0 * 8; \
        cp16(sb + so + ((((uint32_t)c_ch0)     ^ st_swz) << 4), ag); \
        cp16(sb + so + ((((uint32_t)c_ch0 + 1) ^ st_swz) << 4), ag + 8); \
        cp16(sb + so + 8192 + ((((uint32_t)c_ch0)     ^ st_swz) << 4), bg); \
        cp16(sb + so + 8192 + ((((uint32_t)c_ch0 + 1) ^ st_swz) << 4), bg + 8); \
    } while (0)

    HISSUE(0, 0); CP_COMMIT();
    HISSUE(1, 1); CP_COMMIT();
    HISSUE(2, 2); CP_COMMIT();

    for (int it = 0; it < NT; it++) {
        const int s = it - (it / 3) * 3;
        CP_WAIT(2);
        __syncthreads();

        const uint32_t soff = (uint32_t)s * CSTG;

#pragma unroll
        for (int kk = 0; kk < 2; kk++) {
            const uint32_t ac = (((uint32_t)(2 * kk) + a_ch) ^ a_swz) << 4;
            const uint32_t bc = (((uint32_t)(2 * kk) + b_ch) ^ b_swz) << 4;
            uint32_t af[4][4], bf[4][2];
#pragma unroll
            for (int mt = 0; mt < 4; mt++)
                ldmx4(af[mt][0], af[mt][1], af[mt][2], af[mt][3],
                      sb + soff + a_rb + (uint32_t)(mt * 1024) + ac);
            ldmx4(bf[0][0], bf[0][1], bf[1][0], bf[1][1], sb + soff + b_rb + bc);
            ldmx4(bf[2][0], bf[2][1], bf[3][0], bf[3][1], sb + soff + b_rb + 1024 + bc);
#pragma unroll
            for (int mt = 0; mt < 4; mt++)
#pragma unroll
                for (int nt = 0; nt < 4; nt++)
                    mma_f16(acc[mt][nt], af[mt], bf[nt]);
        }
        __syncthreads();
        if (it + 3 < NT) HISSUE(it + 3, s);
        CP_COMMIT();                       // empty group at tail keeps count exact
    }

#pragma unroll
    for (int mt = 0; mt < 4; mt++) {
#pragma unroll
        for (int nt = 0; nt < 4; nt++) {
            const int row = bm + warp_m * 64 + mt * 16 + g;
            const int col = bn + warp_n * 32 + nt * 8 + tg * 2;
            float v0 = acc[mt][nt][0], v1 = acc[mt][nt][1];
            float v2 = acc[mt][nt][2], v3 = acc[mt][nt][3];
            const float b0 = bias[col], b1 = bias[col + 1];
            v0 += b0; v1 += b1; v2 += b0; v3 += b1;
            if (RELU) {
                v0 = fmaxf(v0, 0.f); v1 = fmaxf(v1, 0.f);
                v2 = fmaxf(v2, 0.f); v3 = fmaxf(v3, 0.f);
            }
            if (HASRES) {
                const float* r0p = res + (size_t)row * N + col;
                const float* r1p = res + (size_t)(row + 8) * N + col;
                v0 += r0p[0]; v1 += r0p[1];
                v2 += r1p[0]; v3 += r1p[1];
            }
            if (WRITEH) {
                *(__half2*)(Ch + (size_t)row * N + col) = __floats2half2_rn(v0, v1);
                *(__half2*)(Ch + (size_t)(row + 8) * N + col) = __floats2half2_rn(v2, v3);
            } else {
                *(float2*)(C + (size_t)row * N + col) = make_float2(v0, v1);
                *(float2*)(C + (size_t)(row + 8) * N + col) = make_float2(v2, v3);
            }
        }
    }
#undef HISSUE
}

// ---------------------------------------------------------------------------
// fp16 tensor-core causal flash attention (m16n8k16).  [R12-identical]
// Block: 128 threads (4 warps), one (b,h), 64-query tile; warp = 16 q rows.
// S accum layout == P A-operand layout (no shuffles); V via ldmatrix.x4.trans.
// ---------------------------------------------------------------------------
__global__ __launch_bounds__(128, 3) void attn_h_kernel(
    const __half* __restrict__ qkv, __half* __restrict__ out)
{
    __shared__ __align__(16) __half Ks[64][72];
    __shared__ __align__(16) __half Vs[64][72];

    const int tid = threadIdx.x, wid = tid >> 5, lane = tid & 31;
    const int g = lane >> 2, tg = lane & 3;
    const int qt = gridDim.x - 1 - blockIdx.x;     // longest tiles first
    const int bh = blockIdx.y;
    const int b = bh >> 4, h = bh & 15;
    const int qbase = qt * 64;
    const int wr = wid * 16;

    const uint32_t sK = smem_u32(&Ks[0][0]);
    const uint32_t sV = smem_u32(&Vs[0][0]);

    // ---- stage Q tile (64 x 64 halves) through Ks, build fragments ----
    for (int i = tid; i < 64 * 8; i += 128) {
        int row = i >> 3, c8 = i & 7;
        cp16(sK + (uint32_t)(row * 144 + c8 * 16),
             qkv + (size_t)(b * TT + qbase + row) * 3 * DD + h * HSZ + c8 * 8);
    }
    CP_COMMIT(); CP_WAIT(0);
    __syncthreads();

    const __half2 qsc = __float2half2_rn(0.125f);
    uint32_t qa[4][4];
#pragma unroll
    for (int kk = 0; kk < 4; kk++) {
        __half2 v0 = __hmul2(*(__half2*)&Ks[wr + g][kk * 16 + 2 * tg], qsc);
        __half2 v1 = __hmul2(*(__half2*)&Ks[wr + g + 8][kk * 16 + 2 * tg], qsc);
        __half2 v2 = __hmul2(*(__half2*)&Ks[wr + g][kk * 16 + 2 * tg + 8], qsc);
        __half2 v3 = __hmul2(*(__half2*)&Ks[wr + g + 8][kk * 16 + 2 * tg + 8], qsc);
        qa[kk][0] = *(uint32_t*)&v0; qa[kk][1] = *(uint32_t*)&v1;
        qa[kk][2] = *(uint32_t*)&v2; qa[kk][3] = *(uint32_t*)&v3;
    }
    __syncthreads();

    // ldmatrix lane base address into Vs
    const int lrow = lane & 7;
    const int ksel = (lane >> 3) & 1;      // k rows 0-7 vs 8-15 (j offset +8)
    const int dsel = lane >> 4;            // d cols 0-7 vs 8-15 (+16 B)
    const uint32_t vbase = sV + (uint32_t)((ksel * 8 + lrow) * 144 + dsel * 16);

    float o[8][4] = {};
    float m0 = -1e30f, m1 = -1e30f, l0 = 0.0f, l1 = 0.0f;

    const int nchunks = qt + 1;
    for (int c = 0; c < nchunks; c++) {
        // ---- load K,V chunk (64 x 64 halves each) ----
        for (int i = tid; i < 64 * 8; i += 128) {
            int row = i >> 3, c8 = i & 7;
            const __half* base = qkv + (size_t)(b * TT + c * 64 + row) * 3 * DD + DD + h * HSZ + c8 * 8;
            cp16(sK + (uint32_t)(row * 144 + c8 * 16), base);
            cp16(sV + (uint32_t)(row * 144 + c8 * 16), base + DD);
        }
        CP_COMMIT(); CP_WAIT(0);
        __syncthreads();

        // ---- S = Q K^T ----
        float s[8][4];
#pragma unroll
        for (int nt = 0; nt < 8; nt++) {
            s[nt][0] = 0.f; s[nt][1] = 0.f; s[nt][2] = 0.f; s[nt][3] = 0.f;
            const int j = nt * 8 + g;
#pragma unroll
            for (int kk = 0; kk < 4; kk++) {
                uint32_t bfr[2];
                bfr[0] = *(const uint32_t*)&Ks[j][kk * 16 + 2 * tg];
                bfr[1] = *(const uint32_t*)&Ks[j][kk * 16 + 2 * tg + 8];
                mma_f16(s[nt], qa[kk], bfr);
            }
        }

        // ---- causal mask on diagonal chunk ----
        if (c == qt) {
            const int r0 = wr + g, r1 = wr + g + 8;
#pragma unroll
            for (int nt = 0; nt < 8; nt++) {
                const int c0i = nt * 8 + 2 * tg, c1i = c0i + 1;
                if (c0i > r0) s[nt][0] = -1e30f;
                if (c1i > r0) s[nt][1] = -1e30f;
                if (c0i > r1) s[nt][2] = -1e30f;
                if (c1i > r1) s[nt][3] = -1e30f;
            }
        }

        // ---- online softmax ----
        float mx0 = -1e30f, mx1 = -1e30f;
#pragma unroll
        for (int nt = 0; nt < 8; nt++) {
            mx0 = fmaxf(mx0, fmaxf(s[nt][0], s[nt][1]));
            mx1 = fmaxf(mx1, fmaxf(s[nt][2], s[nt][3]));
        }
        mx0 = fmaxf(mx0, __shfl_xor_sync(0xFFFFFFFFu, mx0, 1));
        mx0 = fmaxf(mx0, __shfl_xor_sync(0xFFFFFFFFu, mx0, 2));
        mx1 = fmaxf(mx1, __shfl_xor_sync(0xFFFFFFFFu, mx1, 1));
        mx1 = fmaxf(mx1, __shfl_xor_sync(0xFFFFFFFFu, mx1, 2));

        const float mn0 = fmaxf(m0, mx0), mn1 = fmaxf(m1, mx1);
        const float a0 = __expf(m0 - mn0), a1 = __expf(m1 - mn1);
        float sum0 = 0.f, sum1 = 0.f;
#pragma unroll
        for (int nt = 0; nt < 8; nt++) {
            s[nt][0] = __expf(s[nt][0] - mn0);
            s[nt][1] = __expf(s[nt][1] - mn0);
            s[nt][2] = __expf(s[nt][2] - mn1);
            s[nt][3] = __expf(s[nt][3] - mn1);
            sum0 += s[nt][0] + s[nt][1];
            sum1 += s[nt][2] + s[nt][3];
        }
        sum0 += __shfl_xor_sync(0xFFFFFFFFu, sum0, 1);
        sum0 += __shfl_xor_sync(0xFFFFFFFFu, sum0, 2);
        sum1 += __shfl_xor_sync(0xFFFFFFFFu, sum1, 1);
        sum1 += __shfl_xor_sync(0xFFFFFFFFu, sum1, 2);
        l0 = l0 * a0 + sum0;
        l1 = l1 * a1 + sum1;
        m0 = mn0; m1 = mn1;

#pragma unroll
        for (int dt = 0; dt < 8; dt++) {
            o[dt][0] *= a0; o[dt][1] *= a0;
            o[dt][2] *= a1; o[dt][3] *= a1;
        }

        // ---- O += P V (P fragments come straight from S accumulators) ----
#pragma unroll
        for (int js = 0; js < 4; js++) {
            uint32_t pa[4];
            pa[0] = packh2(s[2 * js][0], s[2 * js][1]);
            pa[1] = packh2(s[2 * js][2], s[2 * js][3]);
            pa[2] = packh2(s[2 * js + 1][0], s[2 * js + 1][1]);
            pa[3] = packh2(s[2 * js + 1][2], s[2 * js + 1][3]);
            const uint32_t vrow = vbase + (uint32_t)(js * 16 * 144);
#pragma unroll
            for (int dt = 0; dt < 4; dt++) {
                uint32_t r0, r1, r2, r3;
                ldmx4t(r0, r1, r2, r3, vrow + (uint32_t)(dt * 32));
                uint32_t bA[2] = { r0, r1 };
                uint32_t bB[2] = { r2, r3 };
                mma_f16(o[dt * 2], pa, bA);
                mma_f16(o[dt * 2 + 1], pa, bB);
            }
        }
        __syncthreads();
    }

    // ---- epilogue: O / l -> fp16 out ----
    const float inv0 = 1.0f / l0, inv1 = 1.0f / l1;
    const int row0 = b * TT + qbase + wr + g;
#pragma unroll
    for (int dt = 0; dt < 8; dt++) {
        const int col = h * HSZ + dt * 8 + 2 * tg;
        *(__half2*)(out + (size_t)row0 * DD + col) =
            __floats2half2_rn(o[dt][0] * inv0, o[dt][1] * inv0);
        *(__half2*)(out + (size_t)(row0 + 8) * DD + col) =
            __floats2half2_rn(o[dt][2] * inv1, o[dt][3] * inv1);
    }
}

// ---------------------------------------------------------------------------
// LayerNorm over last dim (1024). WH=1: also write fp16 copy.
// ---------------------------------------------------------------------------
template <int WH>
__global__ __launch_bounds__(256) void ln_kernel(
    const float* __restrict__ in, const float* __restrict__ g,
    const float* __restrict__ be, float* __restrict__ out,
    __half* __restrict__ outh)
{
    int row = blockIdx.x;
    int tid = threadIdx.x;
    const float* x = in + (size_t)row * DD;

    float4 v = *(const float4*)(x + tid * 4);
    float s = v.x + v.y + v.z + v.w;
    float ss = v.x * v.x + v.y * v.y + v.z * v.z + v.w * v.w;

    __shared__ float red[2][8];
#pragma unroll
    for (int off = 16; off > 0; off >>= 1) {
        s += __shfl_xor_sync(0xFFFFFFFFu, s, off);
        ss += __shfl_xor_sync(0xFFFFFFFFu, ss, off);
    }
    int w = tid >> 5;
    if ((tid & 31) == 0) { red[0][w] = s; red[1][w] = ss; }
    __syncthreads();
    float S = 0.f, SS = 0.f;
#pragma unroll
    for (int i = 0; i < 8; i++) { S += red[0][i]; SS += red[1][i]; }

    float mu = S * (1.0f / DD);
    float var = SS * (1.0f / DD) - mu * mu;
    float rinv = rsqrtf(var + 1e-5f);

    float4 gv = *(const float4*)(g + tid * 4);
    float4 bv = *(const float4*)(be + tid * 4);
    float4 ov;
    ov.x = (v.x - mu) * rinv * gv.x + bv.x;
    ov.y = (v.y - mu) * rinv * gv.y + bv.y;
    ov.z = (v.z - mu) * rinv * gv.z + bv.z;
    ov.w = (v.w - mu) * rinv * gv.w + bv.w;
    *(float4*)(out + (size_t)row * DD + tid * 4) = ov;
    if (WH) {
        __half2 h[2];
        h[0] = __floats2half2_rn(ov.x, ov.y);
        h[1] = __floats2half2_rn(ov.z, ov.w);
        *(float2*)(outh + (size_t)row * DD + tid * 4) = *(float2*)h;
    }
}

// ---------------------------------------------------------------------------
// Launch (kernel launches only — no attribute calls, no dynamic smem)
// ---------------------------------------------------------------------------
extern "C" void kernel_launch(void* const* d_in, const int* in_sizes, int n_in,
                              void* d_out, int out_size)
{
    const float* x      = (const float*)d_in[0];
    const float* w_qkv  = (const float*)d_in[1];
    const float* b_qkv  = (const float*)d_in[2];
    const float* w_fc   = (const float*)d_in[3];
    const float* b_fc   = (const float*)d_in[4];
    const float* g1     = (const float*)d_in[5];
    const float* beta1  = (const float*)d_in[6];
    const float* w_ff1  = (const float*)d_in[7];
    const float* b_ff1  = (const float*)d_in[8];
    const float* w_ff2  = (const float*)d_in[9];
    const float* b_ff2  = (const float*)d_in[10];
    const float* g2     = (const float*)d_in[11];
    const float* beta2  = (const float*)d_in[12];
    float* out = (float*)d_out;

    float *buf, *ln1;
    __half *qkvh, *xh, *atth, *ln1h, *ff1h, *wqkvT, *wfcT, *wff1T, *wff2T;
    cudaGetSymbolAddress((void**)&buf, g_buf);
    cudaGetSymbolAddress((void**)&ln1, g_ln1);
    cudaGetSymbolAddress((void**)&qkvh, g_qkvh);
    cudaGetSymbolAddress((void**)&xh, g_xh);
    cudaGetSymbolAddress((void**)&atth, g_atth);
    cudaGetSymbolAddress((void**)&ln1h, g_ln1h);
    cudaGetSymbolAddress((void**)&ff1h, g_ff1h);
    cudaGetSymbolAddress((void**)&wqkvT, g_wqkvT);
    cudaGetSymbolAddress((void**)&wfcT, g_wfcT);
    cudaGetSymbolAddress((void**)&wff1T, g_wff1T);
    cudaGetSymbolAddress((void**)&wff2T, g_wff2T);

    // 0) convert/transpose weights + x (64x32 tiles)
    wtcvt_kernel<<<dim3(DD/64, 3*DD/32), 256>>>(w_qkv, wqkvT, DD, 3*DD);
    wtcvt_kernel<<<dim3(DD/64, DD/32), 256>>>(w_fc, wfcT, DD, DD);
    wtcvt_kernel<<<dim3(DD/64, FFD/32), 256>>>(w_ff1, wff1T, DD, FFD);
    wtcvt_kernel<<<dim3(FFD/64, DD/32), 256>>>(w_ff2, wff2T, FFD, DD);
    f2h_kernel<<<(MR*DD)/2048, 256>>>(x, xh);

    // 1) qkvh = fp16(x @ w_qkv + b_qkv)         [4096, 3072]
    hgemm<0,0,1><<<dim3(3*DD/128, MR/128), 256>>>(
        xh, wqkvT, b_qkv, nullptr, nullptr, qkvh, MR, 3*DD, DD);

    // 2) attention (fp16 mma) -> fp16 att
    attn_h_kernel<<<dim3(TT/64, BB*HH), 128>>>(qkvh, atth);

    // 3) buf = att @ w_fc + b_fc + x (residual fused) fp32
    hgemm<0,1,0><<<dim3(DD/128, MR/128), 256>>>(
        atth, wfcT, b_fc, x, buf, nullptr, MR, DD, DD);

    // 4) ln1 = LN(buf) -> fp32 + fp16
    ln_kernel<1><<<MR, 256>>>(buf, g1, beta1, ln1, ln1h);

    // 5) ff1h = relu(ln1 @ w_ff1 + b_ff1) fp16 only
    hgemm<1,0,1><<<dim3(FFD/128, MR/128), 256>>>(
        ln1h, wff1T, b_ff1, nullptr, nullptr, ff1h, MR, FFD, DD);

    // 6) buf = ff1 @ w_ff2 + b_ff2 + ln1 (residual fused, no split-K)
    hgemm<0,1,0><<<dim3(DD/128, MR/128), 256>>>(
        ff1h, wff2T, b_ff2, ln1, buf, nullptr, MR, DD, FFD);

    // 7) out = LN(buf)
    ln_kernel<0><<<MR, 256>>>(buf, g2, beta2, out, nullptr);
}

// round 16
// speedup vs baseline: 1.1083x; 1.0330x over previous
#include <cuda_runtime.h>
#include <cuda_fp16.h>
#include <math.h>
#include <stdint.h>

// Problem constants
#define BB 2
#define TT 2048
#define DD 1024
#define HH 16
#define HSZ 64
#define FFD 16384
#define MR (BB*TT)          // 4096 rows

// ---------------------------------------------------------------------------
// Scratch (static device globals; no runtime allocation)
// ---------------------------------------------------------------------------
__device__ float g_buf[(size_t)MR * DD];         // 16 MB
__device__ float g_ln1[(size_t)MR * DD];         // 16 MB
__device__ __half g_qkvh[(size_t)MR * 3 * DD];   // 25 MB
__device__ __half g_xh[(size_t)MR * DD];
__device__ __half g_atth[(size_t)MR * DD];
__device__ __half g_ln1h[(size_t)MR * DD];
__device__ __half g_ff1h[(size_t)MR * FFD];      // 128 MB
__device__ __half g_wqkvT[(size_t)3 * DD * DD];
__device__ __half g_wfcT[(size_t)DD * DD];
__device__ __half g_wff1T[(size_t)FFD * DD];
__device__ __half g_wff2T[(size_t)DD * FFD];

// ---------------------------------------------------------------------------
// PTX helpers (plain sm_100 legal: mma.sync + cp.async + ldmatrix only)
// ---------------------------------------------------------------------------
__device__ __forceinline__ uint32_t smem_u32(const void* p) {
    uint32_t a;
    asm("{ .reg .u64 t; cvta.to.shared.u64 t, %1; cvt.u32.u64 %0, t; }" : "=r"(a) : "l"(p));
    return a;
}
__device__ __forceinline__ void cp16(uint32_t dst, const void* src) {
    asm volatile("cp.async.cg.shared.global [%0], [%1], 16;" :: "r"(dst), "l"(src) : "memory");
}
#define CP_COMMIT() asm volatile("cp.async.commit_group;" ::: "memory")
#define CP_WAIT(n)  asm volatile("cp.async.wait_group %0;" :: "n"(n) : "memory")

__device__ __forceinline__ void mma_f16(float* c, const uint32_t* a, const uint32_t* b) {
    asm volatile("mma.sync.aligned.m16n8k16.row.col.f32.f16.f16.f32 "
        "{%0,%1,%2,%3}, {%4,%5,%6,%7}, {%8,%9}, {%0,%1,%2,%3};"
        : "+f"(c[0]), "+f"(c[1]), "+f"(c[2]), "+f"(c[3])
        : "r"(a[0]), "r"(a[1]), "r"(a[2]), "r"(a[3]), "r"(b[0]), "r"(b[1]));
}
__device__ __forceinline__ void ldmx4(uint32_t& r0, uint32_t& r1, uint32_t& r2, uint32_t& r3,
                                      uint32_t addr) {
    asm volatile("ldmatrix.sync.aligned.m8n8.x4.shared.b16 {%0,%1,%2,%3}, [%4];"
        : "=r"(r0), "=r"(r1), "=r"(r2), "=r"(r3) : "r"(addr));
}
__device__ __forceinline__ void ldmx4t(uint32_t& r0, uint32_t& r1, uint32_t& r2, uint32_t& r3,
                                       uint32_t addr) {
    asm volatile("ldmatrix.sync.aligned.m8n8.x4.trans.shared.b16 {%0,%1,%2,%3}, [%4];"
        : "=r"(r0), "=r"(r1), "=r"(r2), "=r"(r3) : "r"(addr));
}
__device__ __forceinline__ uint32_t packh2(float a, float b) {
    __half2 h = __floats2half2_rn(a, b);
    return *(uint32_t*)&h;
}

// ---------------------------------------------------------------------------
// Weight convert + transpose: Wt[n][k] = (half)W[k][n]
// Tile 64(K) x 32(N); 16B vectorized stores. [R14-identical]
// ---------------------------------------------------------------------------
__global__ __launch_bounds__(256) void wtcvt_kernel(
    const float* __restrict__ W, __half* __restrict__ Wt, int K, int N)
{
    __shared__ float t[64][33];
    const int k0 = blockIdx.x * 64, n0 = blockIdx.y * 32;
    const int tx = threadIdx.x & 31, ty = threadIdx.x >> 5;   // 32 x 8
#pragma unroll
    for (int i = 0; i < 8; i++)
        t[ty + 8 * i][tx] = W[(size_t)(k0 + ty + 8 * i) * N + n0 + tx];
    __syncthreads();
    const int r = threadIdx.x >> 3;           // 0..31 (n-row within tile)
    const int cg = (threadIdx.x & 7) * 8;     // 0..56 (k-col group of 8)
    __half2 h[4];
#pragma unroll
    for (int j = 0; j < 4; j++)
        h[j] = __floats2half2_rn(t[cg + 2 * j][r], t[cg + 2 * j + 1][r]);
    *(float4*)(Wt + (size_t)(n0 + r) * K + k0 + cg) = *(float4*)h;
}

// x fp32 -> fp16 (8 elements per thread)
__global__ __launch_bounds__(256) void f2h_kernel(
    const float* __restrict__ in, __half* __restrict__ out)
{
    size_t i = ((size_t)blockIdx.x * 256 + threadIdx.x) * 8;
    float4 a = *(const float4*)(in + i);
    float4 b = *(const float4*)(in + i + 4);
    __half2 h[4];
    h[0] = __floats2half2_rn(a.x, a.y);
    h[1] = __floats2half2_rn(a.z, a.w);
    h[2] = __floats2half2_rn(b.x, b.y);
    h[3] = __floats2half2_rn(b.z, b.w);
    *(float4*)(out + i) = *(float4*)h;
}

// ---------------------------------------------------------------------------
// fp16 tensor-core GEMM: C[M,N] = A[M,K] @ Wt^T (Wt is [N,K] fp16)
// BM=BN=128, BK=32, 256 threads (8 warps 2x4), warp tile 64x32.
// 3-stage cp.async ring, chunk XOR swizzle, SINGLE barrier per K-iter:
// prefetch it+2 into the stage consumed at it-1, right after wait+sync.
// WRITEH: write fp16 to Ch instead of fp32 to C.
// ---------------------------------------------------------------------------
#define CSTG 16384                    // bytes per stage (A 8192 + B 8192)

template <int RELU, int HASRES, int WRITEH>
__global__ __launch_bounds__(256, 2) void hgemm(
    const __half* __restrict__ A, const __half* __restrict__ Bt,
    const float* __restrict__ bias, const float* __restrict__ res,
    float* __restrict__ C, __half* __restrict__ Ch, int M, int N, int Kt)
{
    __shared__ __half hs[3 * CSTG / 2];      // 3 stages x 16384 B = 49152 B

    const int tid = threadIdx.x;
    const int wid = tid >> 5, lane = tid & 31;
    const int g = lane >> 2, tg = lane & 3;
    const int warp_m = wid & 1, warp_n = wid >> 1;
    const int bm = blockIdx.y * 128, bn = blockIdx.x * 128;
    const int NT = Kt / 32;
    const uint32_t sb = smem_u32(hs);

    // ldmatrix per-lane mapping (tile order identical to R12; chunk swizzled)
    const int li = lane >> 3, lr = lane & 7;
    const int a_row = warp_m * 64 + (li & 1) * 8 + lr;
    const uint32_t a_ch  = (uint32_t)(li >> 1);
    const uint32_t a_swz = (uint32_t)((a_row >> 1) & 3);
    const uint32_t a_rb  = (uint32_t)(a_row * 64);
    const int b_row = warp_n * 32 + (li >> 1) * 8 + lr;
    const uint32_t b_ch  = (uint32_t)(li & 1);
    const uint32_t b_swz = (uint32_t)((b_row >> 1) & 3);
    const uint32_t b_rb  = (uint32_t)(b_row * 64) + 8192;

    float acc[4][4][4] = {};

    const int c_row = tid >> 1;            // 0..127
    const int c_ch0 = (tid & 1) * 2;       // chunk base {0,2}; 16B chunks
    const uint32_t st_swz = (uint32_t)((c_row >> 1) & 3);
    const uint32_t st_rb  = (uint32_t)(c_row * 64);

#define HISSUE(it, s) do { \
        const int k0 = (it) * 32; \
        const uint32_t so = (uint32_t)(s) * CSTG + st_rb; \
        const __half* ag = A  + (size_t)(bm + c_row) * Kt + k0 + c_ch0 * 8; \
        const __half* bg = Bt + (size_t)(bn + c_row) * Kt + k0 + c_ch0 * 8; \
        cp16(sb + so + ((((uint32_t)c_ch0)     ^ st_swz) << 4), ag); \
        cp16(sb + so + ((((uint32_t)c_ch0 + 1) ^ st_swz) << 4), ag + 8); \
        cp16(sb + so + 8192 + ((((uint32_t)c_ch0)     ^ st_swz) << 4), bg); \
        cp16(sb + so + 8192 + ((((uint32_t)c_ch0 + 1) ^ st_swz) << 4), bg + 8); \
    } while (0)

    HISSUE(0, 0); CP_COMMIT();
    HISSUE(1, 1); CP_COMMIT();

    for (int it = 0; it < NT; it++) {
        const int s = it - (it / 3) * 3;
        CP_WAIT(1);
        __syncthreads();

        // prefetch it+2 into the stage consumed at iter it-1 (safe: all warps
        // passed this barrier, hence finished reading it at the end of it-1)
        if (it + 2 < NT) {
            const int sp = (it + 2) - ((it + 2) / 3) * 3;
            HISSUE(it + 2, sp);
        }
        CP_COMMIT();                       // empty group at tail keeps count exact

        const uint32_t soff = (uint32_t)s * CSTG;

#pragma unroll
        for (int kk = 0; kk < 2; kk++) {
            const uint32_t ac = (((uint32_t)(2 * kk) + a_ch) ^ a_swz) << 4;
            const uint32_t bc = (((uint32_t)(2 * kk) + b_ch) ^ b_swz) << 4;
            uint32_t af[4][4], bf[4][2];
#pragma unroll
            for (int mt = 0; mt < 4; mt++)
                ldmx4(af[mt][0], af[mt][1], af[mt][2], af[mt][3],
                      sb + soff + a_rb + (uint32_t)(mt * 1024) + ac);
            ldmx4(bf[0][0], bf[0][1], bf[1][0], bf[1][1], sb + soff + b_rb + bc);
            ldmx4(bf[2][0], bf[2][1], bf[3][0], bf[3][1], sb + soff + b_rb + 1024 + bc);
#pragma unroll
            for (int mt = 0; mt < 4; mt++)
#pragma unroll
                for (int nt = 0; nt < 4; nt++)
                    mma_f16(acc[mt][nt], af[mt], bf[nt]);
        }
    }

#pragma unroll
    for (int mt = 0; mt < 4; mt++) {
#pragma unroll
        for (int nt = 0; nt < 4; nt++) {
            const int row = bm + warp_m * 64 + mt * 16 + g;
            const int col = bn + warp_n * 32 + nt * 8 + tg * 2;
            float v0 = acc[mt][nt][0], v1 = acc[mt][nt][1];
            float v2 = acc[mt][nt][2], v3 = acc[mt][nt][3];
            const float b0 = bias[col], b1 = bias[col + 1];
            v0 += b0; v1 += b1; v2 += b0; v3 += b1;
            if (RELU) {
                v0 = fmaxf(v0, 0.f); v1 = fmaxf(v1, 0.f);
                v2 = fmaxf(v2, 0.f); v3 = fmaxf(v3, 0.f);
            }
            if (HASRES) {
                const float* r0p = res + (size_t)row * N + col;
                const float* r1p = res + (size_t)(row + 8) * N + col;
                v0 += r0p[0]; v1 += r0p[1];
                v2 += r1p[0]; v3 += r1p[1];
            }
            if (WRITEH) {
                *(__half2*)(Ch + (size_t)row * N + col) = __floats2half2_rn(v0, v1);
                *(__half2*)(Ch + (size_t)(row + 8) * N + col) = __floats2half2_rn(v2, v3);
            } else {
                *(float2*)(C + (size_t)row * N + col) = make_float2(v0, v1);
                *(float2*)(C + (size_t)(row + 8) * N + col) = make_float2(v2, v3);
            }
        }
    }
#undef HISSUE
}

// ---------------------------------------------------------------------------
// fp16 tensor-core causal flash attention (m16n8k16).  [R12-identical]
// Block: 128 threads (4 warps), one (b,h), 64-query tile; warp = 16 q rows.
// S accum layout == P A-operand layout (no shuffles); V via ldmatrix.x4.trans.
// ---------------------------------------------------------------------------
__global__ __launch_bounds__(128, 3) void attn_h_kernel(
    const __half* __restrict__ qkv, __half* __restrict__ out)
{
    __shared__ __align__(16) __half Ks[64][72];
    __shared__ __align__(16) __half Vs[64][72];

    const int tid = threadIdx.x, wid = tid >> 5, lane = tid & 31;
    const int g = lane >> 2, tg = lane & 3;
    const int qt = gridDim.x - 1 - blockIdx.x;     // longest tiles first
    const int bh = blockIdx.y;
    const int b = bh >> 4, h = bh & 15;
    const int qbase = qt * 64;
    const int wr = wid * 16;

    const uint32_t sK = smem_u32(&Ks[0][0]);
    const uint32_t sV = smem_u32(&Vs[0][0]);

    // ---- stage Q tile (64 x 64 halves) through Ks, build fragments ----
    for (int i = tid; i < 64 * 8; i += 128) {
        int row = i >> 3, c8 = i & 7;
        cp16(sK + (uint32_t)(row * 144 + c8 * 16),
             qkv + (size_t)(b * TT + qbase + row) * 3 * DD + h * HSZ + c8 * 8);
    }
    CP_COMMIT(); CP_WAIT(0);
    __syncthreads();

    const __half2 qsc = __float2half2_rn(0.125f);
    uint32_t qa[4][4];
#pragma unroll
    for (int kk = 0; kk < 4; kk++) {
        __half2 v0 = __hmul2(*(__half2*)&Ks[wr + g][kk * 16 + 2 * tg], qsc);
        __half2 v1 = __hmul2(*(__half2*)&Ks[wr + g + 8][kk * 16 + 2 * tg], qsc);
        __half2 v2 = __hmul2(*(__half2*)&Ks[wr + g][kk * 16 + 2 * tg + 8], qsc);
        __half2 v3 = __hmul2(*(__half2*)&Ks[wr + g + 8][kk * 16 + 2 * tg + 8], qsc);
        qa[kk][0] = *(uint32_t*)&v0; qa[kk][1] = *(uint32_t*)&v1;
        qa[kk][2] = *(uint32_t*)&v2; qa[kk][3] = *(uint32_t*)&v3;
    }
    __syncthreads();

    // ldmatrix lane base address into Vs
    const int lrow = lane & 7;
    const int ksel = (lane >> 3) & 1;      // k rows 0-7 vs 8-15 (j offset +8)
    const int dsel = lane >> 4;            // d cols 0-7 vs 8-15 (+16 B)
    const uint32_t vbase = sV + (uint32_t)((ksel * 8 + lrow) * 144 + dsel * 16);

    float o[8][4] = {};
    float m0 = -1e30f, m1 = -1e30f, l0 = 0.0f, l1 = 0.0f;

    const int nchunks = qt + 1;
    for (int c = 0; c < nchunks; c++) {
        // ---- load K,V chunk (64 x 64 halves each) ----
        for (int i = tid; i < 64 * 8; i += 128) {
            int row = i >> 3, c8 = i & 7;
            const __half* base = qkv + (size_t)(b * TT + c * 64 + row) * 3 * DD + DD + h * HSZ + c8 * 8;
            cp16(sK + (uint32_t)(row * 144 + c8 * 16), base);
            cp16(sV + (uint32_t)(row * 144 + c8 * 16), base + DD);
        }
        CP_COMMIT(); CP_WAIT(0);
        __syncthreads();

        // ---- S = Q K^T ----
        float s[8][4];
#pragma unroll
        for (int nt = 0; nt < 8; nt++) {
            s[nt][0] = 0.f; s[nt][1] = 0.f; s[nt][2] = 0.f; s[nt][3] = 0.f;
            const int j = nt * 8 + g;
#pragma unroll
            for (int kk = 0; kk < 4; kk++) {
                uint32_t bfr[2];
                bfr[0] = *(const uint32_t*)&Ks[j][kk * 16 + 2 * tg];
                bfr[1] = *(const uint32_t*)&Ks[j][kk * 16 + 2 * tg + 8];
                mma_f16(s[nt], qa[kk], bfr);
            }
        }

        // ---- causal mask on diagonal chunk ----
        if (c == qt) {
            const int r0 = wr + g, r1 = wr + g + 8;
#pragma unroll
            for (int nt = 0; nt < 8; nt++) {
                const int c0i = nt * 8 + 2 * tg, c1i = c0i + 1;
                if (c0i > r0) s[nt][0] = -1e30f;
                if (c1i > r0) s[nt][1] = -1e30f;
                if (c0i > r1) s[nt][2] = -1e30f;
                if (c1i > r1) s[nt][3] = -1e30f;
            }
        }

        // ---- online softmax ----
        float mx0 = -1e30f, mx1 = -1e30f;
#pragma unroll
        for (int nt = 0; nt < 8; nt++) {
            mx0 = fmaxf(mx0, fmaxf(s[nt][0], s[nt][1]));
            mx1 = fmaxf(mx1, fmaxf(s[nt][2], s[nt][3]));
        }
        mx0 = fmaxf(mx0, __shfl_xor_sync(0xFFFFFFFFu, mx0, 1));
        mx0 = fmaxf(mx0, __shfl_xor_sync(0xFFFFFFFFu, mx0, 2));
        mx1 = fmaxf(mx1, __shfl_xor_sync(0xFFFFFFFFu, mx1, 1));
        mx1 = fmaxf(mx1, __shfl_xor_sync(0xFFFFFFFFu, mx1, 2));

        const float mn0 = fmaxf(m0, mx0), mn1 = fmaxf(m1, mx1);
        const float a0 = __expf(m0 - mn0), a1 = __expf(m1 - mn1);
        float sum0 = 0.f, sum1 = 0.f;
#pragma unroll
        for (int nt = 0; nt < 8; nt++) {
            s[nt][0] = __expf(s[nt][0] - mn0);
            s[nt][1] = __expf(s[nt][1] - mn0);
            s[nt][2] = __expf(s[nt][2] - mn1);
            s[nt][3] = __expf(s[nt][3] - mn1);
            sum0 += s[nt][0] + s[nt][1];
            sum1 += s[nt][2] + s[nt][3];
        }
        sum0 += __shfl_xor_sync(0xFFFFFFFFu, sum0, 1);
        sum0 += __shfl_xor_sync(0xFFFFFFFFu, sum0, 2);
        sum1 += __shfl_xor_sync(0xFFFFFFFFu, sum1, 1);
        sum1 += __shfl_xor_sync(0xFFFFFFFFu, sum1, 2);
        l0 = l0 * a0 + sum0;
        l1 = l1 * a1 + sum1;
        m0 = mn0; m1 = mn1;

#pragma unroll
        for (int dt = 0; dt < 8; dt++) {
            o[dt][0] *= a0; o[dt][1] *= a0;
            o[dt][2] *= a1; o[dt][3] *= a1;
        }

        // ---- O += P V (P fragments come straight from S accumulators) ----
#pragma unroll
        for (int js = 0; js < 4; js++) {
            uint32_t pa[4];
            pa[0] = packh2(s[2 * js][0], s[2 * js][1]);
            pa[1] = packh2(s[2 * js][2], s[2 * js][3]);
            pa[2] = packh2(s[2 * js + 1][0], s[2 * js + 1][1]);
            pa[3] = packh2(s[2 * js + 1][2], s[2 * js + 1][3]);
            const uint32_t vrow = vbase + (uint32_t)(js * 16 * 144);
#pragma unroll
            for (int dt = 0; dt < 4; dt++) {
                uint32_t r0, r1, r2, r3;
                ldmx4t(r0, r1, r2, r3, vrow + (uint32_t)(dt * 32));
                uint32_t bA[2] = { r0, r1 };
                uint32_t bB[2] = { r2, r3 };
                mma_f16(o[dt * 2], pa, bA);
                mma_f16(o[dt * 2 + 1], pa, bB);
            }
        }
        __syncthreads();
    }

    // ---- epilogue: O / l -> fp16 out ----
    const float inv0 = 1.0f / l0, inv1 = 1.0f / l1;
    const int row0 = b * TT + qbase + wr + g;
#pragma unroll
    for (int dt = 0; dt < 8; dt++) {
        const int col = h * HSZ + dt * 8 + 2 * tg;
        *(__half2*)(out + (size_t)row0 * DD + col) =
            __floats2half2_rn(o[dt][0] * inv0, o[dt][1] * inv0);
        *(__half2*)(out + (size_t)(row0 + 8) * DD + col) =
            __floats2half2_rn(o[dt][2] * inv1, o[dt][3] * inv1);
    }
}

// ---------------------------------------------------------------------------
// LayerNorm over last dim (1024). WH=1: also write fp16 copy.
// ---------------------------------------------------------------------------
template <int WH>
__global__ __launch_bounds__(256) void ln_kernel(
    const float* __restrict__ in, const float* __restrict__ g,
    const float* __restrict__ be, float* __restrict__ out,
    __half* __restrict__ outh)
{
    int row = blockIdx.x;
    int tid = threadIdx.x;
    const float* x = in + (size_t)row * DD;

    float4 v = *(const float4*)(x + tid * 4);
    float s = v.x + v.y + v.z + v.w;
    float ss = v.x * v.x + v.y * v.y + v.z * v.z + v.w * v.w;

    __shared__ float red[2][8];
#pragma unroll
    for (int off = 16; off > 0; off >>= 1) {
        s += __shfl_xor_sync(0xFFFFFFFFu, s, off);
        ss += __shfl_xor_sync(0xFFFFFFFFu, ss, off);
    }
    int w = tid >> 5;
    if ((tid & 31) == 0) { red[0][w] = s; red[1][w] = ss; }
    __syncthreads();
    float S = 0.f, SS = 0.f;
#pragma unroll
    for (int i = 0; i < 8; i++) { S += red[0][i]; SS += red[1][i]; }

    float mu = S * (1.0f / DD);
    float var = SS * (1.0f / DD) - mu * mu;
    float rinv = rsqrtf(var + 1e-5f);

    float4 gv = *(const float4*)(g + tid * 4);
    float4 bv = *(const float4*)(be + tid * 4);
    float4 ov;
    ov.x = (v.x - mu) * rinv * gv.x + bv.x;
    ov.y = (v.y - mu) * rinv * gv.y + bv.y;
    ov.z = (v.z - mu) * rinv * gv.z + bv.z;
    ov.w = (v.w - mu) * rinv * gv.w + bv.w;
    *(float4*)(out + (size_t)row * DD + tid * 4) = ov;
    if (WH) {
        __half2 h[2];
        h[0] = __floats2half2_rn(ov.x, ov.y);
        h[1] = __floats2half2_rn(ov.z, ov.w);
        *(float2*)(outh + (size_t)row * DD + tid * 4) = *(float2*)h;
    }
}

// ---------------------------------------------------------------------------
// Launch (kernel launches only — no attribute calls, no dynamic smem)
// ---------------------------------------------------------------------------
extern "C" void kernel_launch(void* const* d_in, const int* in_sizes, int n_in,
                              void* d_out, int out_size)
{
    const float* x      = (const float*)d_in[0];
    const float* w_qkv  = (const float*)d_in[1];
    const float* b_qkv  = (const float*)d_in[2];
    const float* w_fc   = (const float*)d_in[3];
    const float* b_fc   = (const float*)d_in[4];
    const float* g1     = (const float*)d_in[5];
    const float* beta1  = (const float*)d_in[6];
    const float* w_ff1  = (const float*)d_in[7];
    const float* b_ff1  = (const float*)d_in[8];
    const float* w_ff2  = (const float*)d_in[9];
    const float* b_ff2  = (const float*)d_in[10];
    const float* g2     = (const float*)d_in[11];
    const float* beta2  = (const float*)d_in[12];
    float* out = (float*)d_out;

    float *buf, *ln1;
    __half *qkvh, *xh, *atth, *ln1h, *ff1h, *wqkvT, *wfcT, *wff1T, *wff2T;
    cudaGetSymbolAddress((void**)&buf, g_buf);
    cudaGetSymbolAddress((void**)&ln1, g_ln1);
    cudaGetSymbolAddress((void**)&qkvh, g_qkvh);
    cudaGetSymbolAddress((void**)&xh, g_xh);
    cudaGetSymbolAddress((void**)&atth, g_atth);
    cudaGetSymbolAddress((void**)&ln1h, g_ln1h);
    cudaGetSymbolAddress((void**)&ff1h, g_ff1h);
    cudaGetSymbolAddress((void**)&wqkvT, g_wqkvT);
    cudaGetSymbolAddress((void**)&wfcT, g_wfcT);
    cudaGetSymbolAddress((void**)&wff1T, g_wff1T);
    cudaGetSymbolAddress((void**)&wff2T, g_wff2T);

    // 0) convert/transpose weights + x (64x32 tiles)
    wtcvt_kernel<<<dim3(DD/64, 3*DD/32), 256>>>(w_qkv, wqkvT, DD, 3*DD);
    wtcvt_kernel<<<dim3(DD/64, DD/32), 256>>>(w_fc, wfcT, DD, DD);
    wtcvt_kernel<<<dim3(DD/64, FFD/32), 256>>>(w_ff1, wff1T, DD, FFD);
    wtcvt_kernel<<<dim3(FFD/64, DD/32), 256>>>(w_ff2, wff2T, FFD, DD);
    f2h_kernel<<<(MR*DD)/2048, 256>>>(x, xh);

    // 1) qkvh = fp16(x @ w_qkv + b_qkv)         [4096, 3072]
    hgemm<0,0,1><<<dim3(3*DD/128, MR/128), 256>>>(
        xh, wqkvT, b_qkv, nullptr, nullptr, qkvh, MR, 3*DD, DD);

    // 2) attention (fp16 mma) -> fp16 att
    attn_h_kernel<<<dim3(TT/64, BB*HH), 128>>>(qkvh, atth);

    // 3) buf = att @ w_fc + b_fc + x (residual fused) fp32
    hgemm<0,1,0><<<dim3(DD/128, MR/128), 256>>>(
        atth, wfcT, b_fc, x, buf, nullptr, MR, DD, DD);

    // 4) ln1 = LN(buf) -> fp32 + fp16
    ln_kernel<1><<<MR, 256>>>(buf, g1, beta1, ln1, ln1h);

    // 5) ff1h = relu(ln1 @ w_ff1 + b_ff1) fp16 only
    hgemm<1,0,1><<<dim3(FFD/128, MR/128), 256>>>(
        ln1h, wff1T, b_ff1, nullptr, nullptr, ff1h, MR, FFD, DD);

    // 6) buf = ff1 @ w_ff2 + b_ff2 + ln1 (residual fused, no split-K)
    hgemm<0,1,0><<<dim3(DD/128, MR/128), 256>>>(
        ff1h, wff2T, b_ff2, ln1, buf, nullptr, MR, DD, FFD);

    // 7) out = LN(buf)
    ln_kernel<0><<<MR, 256>>>(buf, g2, beta2, out, nullptr);
}